// round 12
// baseline (speedup 1.0000x reference)
#include <cuda_runtime.h>
#include <cuda_bf16.h>
#include <math.h>
#include <stdint.h>

#define BB 2
#define LL 2048
#define DD 1024
#define HH 16
#define DH 64
#define TK 32
#define NCAND 48
#define SCALE 0.125f   // 1/sqrt(64)

// ---------------- scratch (device globals; no allocs allowed) ----------------
__device__ float g_q   [(size_t)BB*LL*DD];
__device__ float g_kv  [(size_t)BB*LL*2*DH];
__device__ float g_k   [(size_t)BB*LL*DH];
__device__ float g_v   [(size_t)BB*LL*DH];
__device__ float g_part[BB*16*128];
__device__ float g_norm[BB*128];
__device__ __nv_bfloat16 g_sims[(size_t)BB*HH*LL*LL];   // 256 MB, bf16 coarse sims
__device__ float g_rowmax[BB*HH*LL];
__device__ float g_rowsum[BB*HH*LL];
__device__ int   g_cand[(size_t)BB*HH*LL*NCAND];
__device__ float g_attn[(size_t)BB*LL*DD];
// bf16 operands
__device__ __nv_bfloat16 g_ah [(size_t)BB*LL*DD];   // attn hi (wconcat)
__device__ __nv_bfloat16 g_al [(size_t)BB*LL*DD];   // attn lo
__device__ __nv_bfloat16 g_bth[(size_t)DD*DD];      // w_concat^T hi
__device__ __nv_bfloat16 g_btl[(size_t)DD*DD];      // w_concat^T lo
__device__ __nv_bfloat16 g_qh [(size_t)BB*LL*DD];   // q bf16 (sims x1)
__device__ __nv_bfloat16 g_kh [(size_t)BB*LL*DH];   // k bf16 (sims x1)
__device__ __nv_bfloat16 g_vth[(size_t)BB*DH*LL];   // v^T hi (pv)
__device__ __nv_bfloat16 g_vtl[(size_t)BB*DH*LL];   // v^T lo

// ---------------- helpers ----------------
__device__ __forceinline__ uint32_t smem_u32(const void* p) {
    uint32_t a;
    asm("{ .reg .u64 t; cvta.to.shared.u64 t, %1; cvt.u32.u64 %0, t; }" : "=r"(a) : "l"(p));
    return a;
}
#define LDSM4(r0, r1, r2, r3, a) \
    asm volatile("ldmatrix.sync.aligned.m8n8.x4.shared.b16 {%0,%1,%2,%3}, [%4];" \
        : "=r"(r0), "=r"(r1), "=r"(r2), "=r"(r3) : "r"(a))
#define MMA_BF16(d, a0, a1, a2, a3, b0, b1) \
    asm volatile("mma.sync.aligned.m16n8k16.row.col.f32.bf16.bf16.f32 " \
        "{%0,%1,%2,%3}, {%4,%5,%6,%7}, {%8,%9}, {%0,%1,%2,%3};" \
        : "+f"((d)[0]), "+f"((d)[1]), "+f"((d)[2]), "+f"((d)[3]) \
        : "r"(a0), "r"(a1), "r"(a2), "r"(a3), "r"(b0), "r"(b1))

__device__ __forceinline__ uint32_t bpack(float a, float b) {
    __nv_bfloat162 t = __floats2bfloat162_rn(a, b);
    return *(uint32_t*)&t;
}
__device__ __forceinline__ unsigned f2key(float x) {
    unsigned u = __float_as_uint(x);
    return u ^ ((unsigned)((int)u >> 31) | 0x80000000u);
}
__device__ __forceinline__ float key2f(unsigned k) {
    unsigned u = (k & 0x80000000u) ? (k ^ 0x80000000u) : ~k;
    return __uint_as_float(u);
}

// ---------------- fragment load / mma helpers ----------------
__device__ __forceinline__ void ld_afrag(uint32_t sb, int base, int wm, int lrow,
                                         int chunk, uint32_t af[4][4]) {
#pragma unroll
    for (int mf = 0; mf < 4; mf++) {
        int row = wm*64 + mf*16 + lrow;
        uint32_t ad = sb + base + row*128 + ((chunk ^ (row & 7)) << 4);
        LDSM4(af[mf][0], af[mf][1], af[mf][2], af[mf][3], ad);
    }
}
__device__ __forceinline__ void ld_bfrag(uint32_t sb, int base, int wn, int lrow,
                                         int chunk, uint32_t bb[4][2]) {
#pragma unroll
    for (int p = 0; p < 2; p++) {
        int row = wn*32 + p*16 + lrow;
        uint32_t bd = sb + base + row*128 + ((chunk ^ (row & 7)) << 4);
        uint32_t t0, t1, t2, t3;
        LDSM4(t0, t1, t2, t3, bd);
        bb[p*2+0][0] = t0; bb[p*2+0][1] = t2;
        bb[p*2+1][0] = t1; bb[p*2+1][1] = t3;
    }
}
__device__ __forceinline__ void do_mma16(float acc[4][4][4], uint32_t af[4][4],
                                         uint32_t bb[4][2]) {
#pragma unroll
    for (int mf = 0; mf < 4; mf++)
#pragma unroll
        for (int nf = 0; nf < 4; nf++)
            MMA_BF16(acc[mf][nf], af[mf][0], af[mf][1], af[mf][2], af[mf][3],
                     bb[nf][0], bb[nf][1]);
}

// ---------------- fp32 SIMT GEMM (wq / kv — bitwise-faithful sequential-k) --
__global__ __launch_bounds__(256) void sgemm_kernel(
    const float* __restrict__ A, const float* __restrict__ Bm,
    float* __restrict__ C, int Mdim, int Ndim, int Kdim)
{
    __shared__ float As[128*33];
    __shared__ float Bs[32*132];
    int tid  = threadIdx.x;
    int brow = blockIdx.y * 128;
    int bcol = blockIdx.x * 128;
    int rowg = tid >> 4;
    int c0   = (tid & 15) * 4;
    float acc[8][8];
#pragma unroll
    for (int i = 0; i < 8; i++)
#pragma unroll
        for (int j = 0; j < 8; j++) acc[i][j] = 0.f;

    for (int kt = 0; kt < Kdim; kt += 32) {
#pragma unroll
        for (int i = 0; i < 4; i++) {
            int f4 = tid + i*256;
            int r = f4 >> 3, c4 = f4 & 7;
            float4 v = *(const float4*)(A + (size_t)(brow + r)*Kdim + kt + c4*4);
            As[r*33 + c4*4+0] = v.x; As[r*33 + c4*4+1] = v.y;
            As[r*33 + c4*4+2] = v.z; As[r*33 + c4*4+3] = v.w;
        }
#pragma unroll
        for (int i = 0; i < 4; i++) {
            int f4 = tid + i*256;
            int r = f4 >> 5, c4 = f4 & 31;
            *(float4*)&Bs[r*132 + c4*4] =
                *(const float4*)(Bm + (size_t)(kt + r)*Ndim + bcol + c4*4);
        }
        __syncthreads();
#pragma unroll 8
        for (int kk = 0; kk < 32; kk++) {
            float av[8];
#pragma unroll
            for (int i = 0; i < 8; i++) av[i] = As[(rowg + 16*i)*33 + kk];
            float4 b0 = *(float4*)&Bs[kk*132 + c0];
            float4 b1 = *(float4*)&Bs[kk*132 + 64 + c0];
#pragma unroll
            for (int i = 0; i < 8; i++) {
                acc[i][0] += av[i]*b0.x; acc[i][1] += av[i]*b0.y;
                acc[i][2] += av[i]*b0.z; acc[i][3] += av[i]*b0.w;
                acc[i][4] += av[i]*b1.x; acc[i][5] += av[i]*b1.y;
                acc[i][6] += av[i]*b1.z; acc[i][7] += av[i]*b1.w;
            }
        }
        __syncthreads();
    }
#pragma unroll
    for (int i = 0; i < 8; i++) {
        size_t r = (size_t)(brow + rowg + 16*i)*Ndim + bcol;
        *(float4*)(C + r + c0)      = make_float4(acc[i][0],acc[i][1],acc[i][2],acc[i][3]);
        *(float4*)(C + r + 64 + c0) = make_float4(acc[i][4],acc[i][5],acc[i][6],acc[i][7]);
    }
}

// ---------------- sims = q @ k^T  (plain bf16 x1 MMA, bf16 output) ----------
// grid (16,16,32), 256 thr, 32KB smem: Ah @0, Bh @16384.
__global__ __launch_bounds__(256) void sims1_kernel()
{
    extern __shared__ char smem[];
    int z = blockIdx.z, b = z >> 4, h = z & 15;
    int lbase = blockIdx.y * 128, mbase = blockIdx.x * 128;
    const __nv_bfloat16* Aq = g_qh + ((size_t)b*LL + lbase)*DD + (size_t)h*DH;
    const __nv_bfloat16* Bk = g_kh + ((size_t)b*LL + mbase)*DH;
    __nv_bfloat16* Cs = g_sims + (size_t)z*LL*LL + (size_t)lbase*LL + mbase;
    uint32_t sb = smem_u32(smem);
    int tid = threadIdx.x, lane = tid & 31, wid = tid >> 5;
    int wm = wid >> 2, wn = wid & 3;
    int lrow = lane & 15, lhalf = lane >> 4;
    float acc[4][4][4];
#pragma unroll
    for (int i = 0; i < 4; i++)
#pragma unroll
        for (int j = 0; j < 4; j++)
#pragma unroll
            for (int q = 0; q < 4; q++) acc[i][j][q] = 0.f;

    int r0 = tid >> 3, cc = tid & 7;
#pragma unroll
    for (int t = 0; t < 4; t++) {       // A tile 128x64
        int r = r0 + t*32;
        *(uint4*)(smem + r*128 + ((cc ^ (r & 7)) << 4)) =
            *(const uint4*)(Aq + (size_t)r*DD + cc*8);
    }
#pragma unroll
    for (int t = 0; t < 4; t++) {       // B tile 128x64
        int r = r0 + t*32;
        *(uint4*)(smem + 16384 + r*128 + ((cc ^ (r & 7)) << 4)) =
            *(const uint4*)(Bk + (size_t)r*DH + cc*8);
    }
    __syncthreads();
#pragma unroll
    for (int s = 0; s < 4; s++) {
        int chunk = s*2 + lhalf;
        uint32_t af[4][4], bb[4][2];
        ld_bfrag(sb, 16384, wn, lrow, chunk, bb);
        ld_afrag(sb, 0,     wm, lrow, chunk, af);
        do_mma16(acc, af, bb);
    }
#pragma unroll
    for (int mf = 0; mf < 4; mf++) {
        int r = wm*64 + mf*16 + (lane >> 2);
#pragma unroll
        for (int nf = 0; nf < 4; nf++) {
            int c = wn*32 + nf*8 + (lane & 3)*2;
            *(uint32_t*)(Cs + (size_t)r*LL + c)       = bpack(acc[mf][nf][0], acc[mf][nf][1]);
            *(uint32_t*)(Cs + (size_t)(r + 8)*LL + c) = bpack(acc[mf][nf][2], acc[mf][nf][3]);
        }
    }
}

// ---------------- bf16x3 GEMM body (wconcat — smooth) -----------------------
__device__ __forceinline__ void mma_gemm_body3(
    const __nv_bfloat16* __restrict__ Ah, const __nv_bfloat16* __restrict__ Al, int lda,
    const __nv_bfloat16* __restrict__ Bh, const __nv_bfloat16* __restrict__ Bl, int ldb,
    float* __restrict__ C, int ldc, int Kdim, char* smem)
{
    uint32_t sb = smem_u32(smem);
    int tid = threadIdx.x, lane = tid & 31, wid = tid >> 5;
    int wm = wid >> 2, wn = wid & 3;
    int lrow = lane & 15, lhalf = lane >> 4;
    float acc[4][4][4];
#pragma unroll
    for (int i = 0; i < 4; i++)
#pragma unroll
        for (int j = 0; j < 4; j++)
#pragma unroll
            for (int q = 0; q < 4; q++) acc[i][j][q] = 0.f;

    int r0 = tid >> 3, cc = tid & 7;
    for (int kt = 0; kt < Kdim; kt += 64) {
#pragma unroll
        for (int t = 0; t < 16; t++) {
            int tile = t >> 2;
            int r = r0 + (t & 3)*32;
            int ld = (tile < 2) ? lda : ldb;
            const __nv_bfloat16* sp =
                ((tile == 0) ? Ah : (tile == 1) ? Al : (tile == 2) ? Bh : Bl)
                + (size_t)r*ld + kt + cc*8;
            *(uint4*)(smem + tile*16384 + r*128 + ((cc ^ (r & 7)) << 4)) = *(const uint4*)sp;
        }
        __syncthreads();
#pragma unroll
        for (int s = 0; s < 4; s++) {
            int chunk = s*2 + lhalf;
            uint32_t af[4][4], bb[4][2];
            ld_bfrag(sb, 32768, wn, lrow, chunk, bb);       // B hi
            ld_afrag(sb, 0,     wm, lrow, chunk, af); do_mma16(acc, af, bb);
            ld_afrag(sb, 16384, wm, lrow, chunk, af); do_mma16(acc, af, bb);
            ld_bfrag(sb, 49152, wn, lrow, chunk, bb);       // B lo
            ld_afrag(sb, 0,     wm, lrow, chunk, af); do_mma16(acc, af, bb);
        }
        __syncthreads();
    }
#pragma unroll
    for (int mf = 0; mf < 4; mf++) {
        int r = wm*64 + mf*16 + (lane >> 2);
#pragma unroll
        for (int nf = 0; nf < 4; nf++) {
            int c = wn*32 + nf*8 + (lane & 3)*2;
            *(float2*)(C + (size_t)r*ldc + c)       = make_float2(acc[mf][nf][0], acc[mf][nf][1]);
            *(float2*)(C + (size_t)(r + 8)*ldc + c) = make_float2(acc[mf][nf][2], acc[mf][nf][3]);
        }
    }
}

__global__ __launch_bounds__(256) void mma_gemm3_kernel(
    const __nv_bfloat16* __restrict__ Ah, const __nv_bfloat16* __restrict__ Al,
    const __nv_bfloat16* __restrict__ Bth, const __nv_bfloat16* __restrict__ Btl,
    float* __restrict__ C, int Ndim, int Kdim)
{
    extern __shared__ char smem[];
    int brow = blockIdx.y * 128, bcol = blockIdx.x * 128;
    mma_gemm_body3(Ah + (size_t)brow*Kdim, Al + (size_t)brow*Kdim, Kdim,
                   Bth + (size_t)bcol*Kdim, Btl + (size_t)bcol*Kdim, Kdim,
                   C + (size_t)brow*Ndim + bcol, Ndim, Kdim, smem);
}

// ---------------- pv: local = softmax(sims)@v via bf16x3 mma (bf16 sims) ----
__global__ __launch_bounds__(256) void pv_mma_kernel()
{
    extern __shared__ char smem[];
    float* smx = (float*)(smem + 49152);
    float* sis = (float*)(smem + 49664);
    int z = blockIdx.y, b = z >> 4, h = z & 15;
    int lbase = blockIdx.x * 128;
    const __nv_bfloat16* S = g_sims + (size_t)z*LL*LL;
    int tid = threadIdx.x, lane = tid & 31, wid = tid >> 5;
    if (tid < 128) {
        size_t row = (size_t)z*LL + lbase + tid;
        smx[tid] = g_rowmax[row];
        sis[tid] = 1.0f / g_rowsum[row];
    }
    __syncthreads();
    uint32_t sb = smem_u32(smem);
    int wm = wid >> 1, wn = wid & 1;
    int lrow = lane & 15, lhalf = lane >> 4;
    float acc[2][4][4];
#pragma unroll
    for (int i = 0; i < 2; i++)
#pragma unroll
        for (int j = 0; j < 4; j++)
#pragma unroll
            for (int q = 0; q < 4; q++) acc[i][j][q] = 0.f;

    int r0 = tid >> 3, cc = tid & 7;
    const __nv_bfloat16* Vh = g_vth + (size_t)b*DH*LL;
    const __nv_bfloat16* Vl = g_vtl + (size_t)b*DH*LL;

    for (int mt = 0; mt < LL; mt += 64) {
#pragma unroll
        for (int t = 0; t < 4; t++) {
            int r = r0 + t*32;
            const __nv_bfloat16* sp = S + (size_t)(lbase + r)*LL + mt + cc*8;
            uint4 raw = *(const uint4*)sp;
            const __nv_bfloat162* pp = (const __nv_bfloat162*)&raw;
            float m = smx[r], is = sis[r];
            float e[8];
#pragma unroll
            for (int j = 0; j < 4; j++) {
                float2 f = __bfloat1622float2(pp[j]);
                e[2*j]   = __expf((f.x - m)*SCALE)*is;
                e[2*j+1] = __expf((f.y - m)*SCALE)*is;
            }
            float hf[8], lf[8];
#pragma unroll
            for (int j = 0; j < 8; j++) {
                hf[j] = __bfloat162float(__float2bfloat16(e[j]));
                lf[j] = e[j] - hf[j];
            }
            uint4 uh = make_uint4(bpack(hf[0],hf[1]), bpack(hf[2],hf[3]),
                                  bpack(hf[4],hf[5]), bpack(hf[6],hf[7]));
            uint4 ul = make_uint4(bpack(lf[0],lf[1]), bpack(lf[2],lf[3]),
                                  bpack(lf[4],lf[5]), bpack(lf[6],lf[7]));
            int off = r*128 + ((cc ^ (r & 7)) << 4);
            *(uint4*)(smem + off)         = uh;
            *(uint4*)(smem + 16384 + off) = ul;
        }
#pragma unroll
        for (int t = 0; t < 2; t++) {
            int idx = tid + t*256;
            int r = idx >> 3, c = idx & 7;
            int off = 32768 + r*128 + ((c ^ (r & 7)) << 4);
            *(uint4*)(smem + off)        = *(const uint4*)(Vh + (size_t)r*LL + mt + c*8);
            *(uint4*)(smem + off + 8192) = *(const uint4*)(Vl + (size_t)r*LL + mt + c*8);
        }
        __syncthreads();
#pragma unroll
        for (int s = 0; s < 4; s++) {
            int chunk = s*2 + lhalf;
            uint32_t ah[2][4], al[2][4], bh[4][2], bl[4][2];
#pragma unroll
            for (int mf = 0; mf < 2; mf++) {
                int row = wm*32 + mf*16 + lrow;
                uint32_t ad = sb + row*128 + ((chunk ^ (row & 7)) << 4);
                LDSM4(ah[mf][0], ah[mf][1], ah[mf][2], ah[mf][3], ad);
                LDSM4(al[mf][0], al[mf][1], al[mf][2], al[mf][3], ad + 16384);
            }
#pragma unroll
            for (int p = 0; p < 2; p++) {
                int row = wn*32 + p*16 + lrow;
                uint32_t bd = sb + 32768 + row*128 + ((chunk ^ (row & 7)) << 4);
                uint32_t t0, t1, t2, t3;
                LDSM4(t0, t1, t2, t3, bd);
                bh[p*2+0][0] = t0; bh[p*2+0][1] = t2;
                bh[p*2+1][0] = t1; bh[p*2+1][1] = t3;
                LDSM4(t0, t1, t2, t3, bd + 8192);
                bl[p*2+0][0] = t0; bl[p*2+0][1] = t2;
                bl[p*2+1][0] = t1; bl[p*2+1][1] = t3;
            }
#pragma unroll
            for (int mf = 0; mf < 2; mf++)
#pragma unroll
                for (int nf = 0; nf < 4; nf++) {
                    MMA_BF16(acc[mf][nf], ah[mf][0], ah[mf][1], ah[mf][2], ah[mf][3],
                             bh[nf][0], bh[nf][1]);
                    MMA_BF16(acc[mf][nf], ah[mf][0], ah[mf][1], ah[mf][2], ah[mf][3],
                             bl[nf][0], bl[nf][1]);
                    MMA_BF16(acc[mf][nf], al[mf][0], al[mf][1], al[mf][2], al[mf][3],
                             bh[nf][0], bh[nf][1]);
                }
        }
        __syncthreads();
    }
#pragma unroll
    for (int mf = 0; mf < 2; mf++) {
        int r = wm*32 + mf*16 + (lane >> 2);
#pragma unroll
        for (int nf = 0; nf < 4; nf++) {
            int c = wn*32 + nf*8 + (lane & 3)*2;
            float* p = g_attn + ((size_t)b*LL + lbase + r)*DD + h*DH + c;
            *(float2*)p                  = make_float2(acc[mf][nf][0], acc[mf][nf][1]);
            *(float2*)(p + (size_t)8*DD) = make_float2(acc[mf][nf][2], acc[mf][nf][3]);
        }
    }
}

// ---------------- split / cast kernels ----------------
__global__ void split_kernel(const float* __restrict__ src,
                             __nv_bfloat16* __restrict__ hi, __nv_bfloat16* __restrict__ lo)
{
    int i = blockIdx.x*256 + threadIdx.x;
    float4 v = ((const float4*)src)[i];
    float vv[4] = {v.x, v.y, v.z, v.w};
#pragma unroll
    for (int j = 0; j < 4; j++) {
        __nv_bfloat16 h = __float2bfloat16(vv[j]);
        hi[i*4 + j] = h;
        lo[i*4 + j] = __float2bfloat16(vv[j] - __bfloat162float(h));
    }
}

__global__ void qcast_kernel(const float* __restrict__ src,
                             __nv_bfloat16* __restrict__ dst)
{
    int i = blockIdx.x*256 + threadIdx.x;
    float4 v = ((const float4*)src)[i];
    uint2 o;
    o.x = bpack(v.x, v.y);
    o.y = bpack(v.z, v.w);
    *(uint2*)(dst + (size_t)i*4) = o;
}

__global__ void transpose_split_kernel(const float* __restrict__ src,
                                       __nv_bfloat16* __restrict__ hi,
                                       __nv_bfloat16* __restrict__ lo, int R, int Cn)
{
    __shared__ float t[32][33];
    int c0 = blockIdx.x*32, r0 = blockIdx.y*32;
    for (int i = threadIdx.y; i < 32; i += 8)
        t[i][threadIdx.x] = src[(size_t)(r0 + i)*Cn + c0 + threadIdx.x];
    __syncthreads();
    for (int i = threadIdx.y; i < 32; i += 8) {
        float x = t[threadIdx.x][i];
        __nv_bfloat16 h = __float2bfloat16(x);
        size_t o = (size_t)(c0 + i)*R + r0 + threadIdx.x;
        hi[o] = h;
        lo[o] = __float2bfloat16(x - __bfloat162float(h));
    }
}

// ---------------- sequence-axis L2 norm ----------------
__global__ void colsq_kernel() {
    int b = blockIdx.x >> 4, chunk = blockIdx.x & 15;
    int j = threadIdx.x & 127, p = threadIdx.x >> 7;
    const float* base = g_kv + ((size_t)b*LL + chunk*128)*128;
    float ss = 0.f;
    for (int ll = p; ll < 128; ll += 2) {
        float v = base[ll*128 + j];
        ss += v*v;
    }
    __shared__ float sh[256];
    sh[threadIdx.x] = ss;
    __syncthreads();
    if (p == 0) g_part[(size_t)blockIdx.x*128 + j] = ss + sh[128 + j];
}

__global__ void normsum_kernel() {
    int tid = threadIdx.x;
    int b = tid >> 7, j = tid & 127;
    float s = 0.f;
    for (int c = 0; c < 16; c++) s += g_part[(b*16 + c)*128 + j];
    g_norm[tid] = s;
}

__global__ void normalize_kernel() {
    int idx = blockIdx.x*256 + threadIdx.x;
    int j  = idx & 127;
    int bl = idx >> 7;
    int b  = bl >> 11;
    float n = sqrtf(g_norm[b*128 + j]);
    n = fmaxf(n, 1e-12f);
    float v = g_kv[(size_t)idx] / n;
    if (j < 64) {
        g_k[(size_t)bl*64 + j]  = v;
        g_kh[(size_t)bl*64 + j] = __float2bfloat16(v);
    } else {
        g_v[(size_t)bl*64 + (j - 64)] = v;
    }
}

// ---------------- per-row: max, sumexp, coarse top-48 (bf16 sims) -----------
__global__ __launch_bounds__(256) void stats_topk_kernel() {  // grid 65536
    __shared__ unsigned cand_key[320];
    __shared__ int      cand_idx[320];
    __shared__ float    redf[8];
    __shared__ unsigned redk[8];
    __shared__ float    s_mx;
    size_t row = blockIdx.x;
    const __nv_bfloat16* S = g_sims + row * LL;
    int tid = threadIdx.x, lane = tid & 31, wid = tid >> 5;

    uint4 raw = ((const uint4*)S)[tid];       // 8 bf16: elements tid*8 .. tid*8+7
    const __nv_bfloat162* pp = (const __nv_bfloat162*)&raw;
    float v[8];
#pragma unroll
    for (int j = 0; j < 4; j++) {
        float2 f = __bfloat1622float2(pp[j]);
        v[2*j] = f.x; v[2*j+1] = f.y;
    }
    unsigned key[8];
#pragma unroll
    for (int j = 0; j < 8; j++) key[j] = f2key(v[j]);

    unsigned km = key[0];
#pragma unroll
    for (int j = 1; j < 8; j++) km = max(km, key[j]);
    km = __reduce_max_sync(0xffffffffu, km);
    if (lane == 0) redk[wid] = km;
    __syncthreads();
    if (tid == 0) {
        unsigned m = redk[0];
        for (int w = 1; w < 8; w++) m = max(m, redk[w]);
        float mx = key2f(m);
        s_mx = mx;
        g_rowmax[row] = mx;
    }
    __syncthreads();
    float mx = s_mx;

    float ls = 0.f;
#pragma unroll
    for (int j = 0; j < 8; j++) ls += __expf((v[j] - mx)*SCALE);
#pragma unroll
    for (int o = 16; o; o >>= 1) ls += __shfl_xor_sync(0xffffffffu, ls, o);
    if (lane == 0) redf[wid] = ls;
    __syncthreads();
    if (tid == 0) {
        float t = 0.f;
        for (int w = 0; w < 8; w++) t += redf[w];
        g_rowsum[row] = t;
    }

    // per-warp top-40 of its 256 elements
    unsigned lk = 0; int lj = 0;
#pragma unroll
    for (int j = 0; j < 8; j++) if (key[j] > lk) { lk = key[j]; lj = j; }
    for (int it = 0; it < 40; it++) {
        unsigned w = __reduce_max_sync(0xffffffffu, lk);
        unsigned ball = __ballot_sync(0xffffffffu, lk == w);
        int src = __ffs(ball) - 1;
        if (lane == src) {
            cand_key[wid*40 + it] = w;
            cand_idx[wid*40 + it] = tid*8 + lj;
            key[lj] = 0u;
            lk = 0; lj = 0;
#pragma unroll
            for (int j = 0; j < 8; j++) if (key[j] > lk) { lk = key[j]; lj = j; }
        }
    }
    __syncthreads();

    // warp 0 merges 320 candidates -> coarse top-48 indices
    if (wid == 0) {
        unsigned mkey[10]; int midx[10];
#pragma unroll
        for (int j = 0; j < 10; j++) {
            mkey[j] = cand_key[lane*10 + j];
            midx[j] = cand_idx[lane*10 + j];
        }
        unsigned mk = 0; int mj = 0;
#pragma unroll
        for (int j = 0; j < 10; j++) if (mkey[j] > mk) { mk = mkey[j]; mj = j; }
        for (int it = 0; it < NCAND; it++) {
            unsigned w = __reduce_max_sync(0xffffffffu, mk);
            unsigned ball = __ballot_sync(0xffffffffu, mk == w);
            int src = __ffs(ball) - 1;
            if (lane == src) {
                g_cand[row*NCAND + it] = midx[mj];
                mkey[mj] = 0u;
                mk = 0; mj = 0;
#pragma unroll
                for (int j = 0; j < 10; j++) if (mkey[j] > mk) { mk = mkey[j]; mj = j; }
            }
        }
    }
}

// ---------------- refine: sequential fp32 re-score + top-32 + retrieved -----
__device__ __forceinline__ float dot64_seq(const float* __restrict__ q,
                                           const float* __restrict__ k) {
    float s = 0.f;
#pragma unroll
    for (int i = 0; i < 64; i++) s = fmaf(q[i], k[i], s);
    return s;
}

__global__ __launch_bounds__(256) void refine_kernel() {  // grid 8192, warp/row
    __shared__ float qrow[8][64];
    __shared__ float sel_v[8][32];
    __shared__ int   sel_i[8][32];
    int wid = threadIdx.x >> 5, lane = threadIdx.x & 31;
    size_t row = (size_t)blockIdx.x*8 + wid;
    int z = (int)(row >> 11), l = (int)(row & 2047);
    int b = z >> 4, h = z & 15;

    const float* qp = g_q + ((size_t)b*LL + l)*DD + (size_t)h*DH;
    qrow[wid][lane]      = qp[lane];
    qrow[wid][lane + 32] = qp[lane + 32];
    __syncwarp();

    const float* kb = g_k + (size_t)b*LL*DH;
    int i0 = g_cand[row*NCAND + lane];
    float v0 = dot64_seq(qrow[wid], kb + (size_t)i0*DH);
    unsigned k0 = f2key(v0);
    int i1 = 0;
    unsigned k1 = 0u;
    if (lane < 16) {
        i1 = g_cand[row*NCAND + 32 + lane];
        float v1 = dot64_seq(qrow[wid], kb + (size_t)i1*DH);
        k1 = f2key(v1);
    }

    unsigned lk; int lj;
    if (k0 >= k1) { lk = k0; lj = 0; } else { lk = k1; lj = 1; }
    for (int it = 0; it < TK; it++) {
        unsigned w = __reduce_max_sync(0xffffffffu, lk);
        unsigned ball = __ballot_sync(0xffffffffu, lk == w);
        int src = __ffs(ball) - 1;
        if (lane == src) {
            sel_v[wid][it] = key2f(w);
            sel_i[wid][it] = (lj == 0) ? i0 : i1;
            if (lj == 0) k0 = 0u; else k1 = 0u;
            if (k0 >= k1) { lk = k0; lj = 0; } else { lk = k1; lj = 1; }
        }
    }
    __syncwarp();

    float tv = sel_v[wid][lane];
    float mx = sel_v[wid][0];
    float p = __expf((tv - mx)*SCALE);
    float psum = p;
#pragma unroll
    for (int o = 16; o; o >>= 1) psum += __shfl_xor_sync(0xffffffffu, psum, o);
    sel_v[wid][lane] = p / psum;
    __syncwarp();

    float a0 = 0.f, a1 = 0.f;
#pragma unroll 8
    for (int t = 0; t < TK; t++) {
        float w = sel_v[wid][t];
        const float* kr = kb + (size_t)sel_i[wid][t]*DH;
        a0 += w * kr[lane];
        a1 += w * kr[lane + 32];
    }
    size_t off = ((size_t)b*LL + l)*DD + (size_t)h*DH;
    g_attn[off + lane]      += a0;
    g_attn[off + lane + 32] += a1;
}

// ---------------- launch ----------------
extern "C" void kernel_launch(void* const* d_in, const int* in_sizes, int n_in,
                              void* d_out, int out_size)
{
    const float* q_in     = (const float*)d_in[0];
    const float* kv_in    = (const float*)d_in[1];
    const float* w_q      = (const float*)d_in[2];
    const float* w_kv     = (const float*)d_in[3];
    const float* w_concat = (const float*)d_in[4];
    float* out = (float*)d_out;

    float *p_q, *p_kv, *p_attn, *p_v;
    __nv_bfloat16 *p_ah, *p_al, *p_bth, *p_btl, *p_qh, *p_vth, *p_vtl;
    cudaGetSymbolAddress((void**)&p_q,    g_q);
    cudaGetSymbolAddress((void**)&p_kv,   g_kv);
    cudaGetSymbolAddress((void**)&p_attn, g_attn);
    cudaGetSymbolAddress((void**)&p_v,    g_v);
    cudaGetSymbolAddress((void**)&p_ah,   g_ah);
    cudaGetSymbolAddress((void**)&p_al,   g_al);
    cudaGetSymbolAddress((void**)&p_bth,  g_bth);
    cudaGetSymbolAddress((void**)&p_btl,  g_btl);
    cudaGetSymbolAddress((void**)&p_qh,   g_qh);
    cudaGetSymbolAddress((void**)&p_vth,  g_vth);
    cudaGetSymbolAddress((void**)&p_vtl,  g_vtl);

    static const int G3_SMEM   = 65536;
    static const int SIMS_SMEM = 32768;
    static const int PV_SMEM   = 50176;
    cudaFuncSetAttribute(mma_gemm3_kernel, cudaFuncAttributeMaxDynamicSharedMemorySize, G3_SMEM);
    cudaFuncSetAttribute(sims1_kernel,     cudaFuncAttributeMaxDynamicSharedMemorySize, SIMS_SMEM);
    cudaFuncSetAttribute(pv_mma_kernel,    cudaFuncAttributeMaxDynamicSharedMemorySize, PV_SMEM);

    // 1. q = q_in @ w_q  (fp32 SIMT — sequential-k, selection-critical)
    sgemm_kernel<<<dim3(8, 32), 256>>>(q_in, w_q, p_q, BB*LL, DD, DD);
    // 2. kv = kv_in @ w_kv  (fp32 SIMT)
    sgemm_kernel<<<dim3(1, 32), 256>>>(kv_in, w_kv, p_kv, BB*LL, 2*DH, DD);
    // 3. l2 norm over sequence axis (+ k bf16 cast)
    colsq_kernel<<<32, 256>>>();
    normsum_kernel<<<1, 256>>>();
    normalize_kernel<<<2048, 256>>>();
    // 3b. v^T 2-split for pv
    transpose_split_kernel<<<dim3(2,64), dim3(32,8)>>>(p_v,          p_vth,         p_vtl,         LL, DH);
    transpose_split_kernel<<<dim3(2,64), dim3(32,8)>>>(p_v + LL*DH,  p_vth + DH*LL, p_vtl + DH*LL, LL, DH);
    // 4. sims = q @ k^T  (plain bf16 x1 MMA, bf16 output — softmax-invariant + candidates)
    qcast_kernel<<<4096, 256>>>(p_q, p_qh);
    sims1_kernel<<<dim3(16,16,32), 256, SIMS_SMEM>>>();
    // 5. row stats + coarse top-48 candidates
    stats_topk_kernel<<<BB*HH*LL, 256>>>();
    // 6. local attention (P@V) -> g_attn  (bf16x3, bf16 sims in)
    pv_mma_kernel<<<dim3(16, 32), 256, PV_SMEM>>>();
    // 7. sequential-fp32 refine + retrieved (+= into g_attn)
    refine_kernel<<<BB*HH*LL/8, 256>>>();
    // 8. out = attn @ w_concat  (bf16x3)
    transpose_split_kernel<<<dim3(32,32), dim3(32,8)>>>(w_concat, p_bth, p_btl, DD, DD);
    split_kernel<<<4096, 256>>>(p_attn, p_ah, p_al);
    mma_gemm3_kernel<<<dim3(8,32), 256, G3_SMEM>>>(p_ah, p_al, p_bth, p_btl, out, DD, DD);
}

// round 13
// speedup vs baseline: 1.7636x; 1.7636x over previous
#include <cuda_runtime.h>
#include <math.h>

#define BB 2
#define LL 2048
#define DD 1024
#define HH 16
#define DH 64
#define TK 32
#define SCALE 0.125f   // 1/sqrt(64)

// ---------------- scratch (device globals; no allocs allowed) ----------------
__device__ float g_q   [(size_t)BB*LL*DD];
__device__ float g_kv  [(size_t)BB*LL*2*DH];
__device__ float g_k   [(size_t)BB*LL*DH];
__device__ float g_v   [(size_t)BB*LL*DH];
__device__ float g_part[BB*16*128];
__device__ float g_norm[BB*128];
__device__ float g_sims[(size_t)BB*HH*LL*LL];       // 512 MB
__device__ float g_rowmax[BB*HH*LL];
__device__ float g_topv[(size_t)BB*HH*LL*TK];
__device__ int   g_topi[(size_t)BB*HH*LL*TK];
__device__ float g_attn[(size_t)BB*LL*DD];

// ordered-uint key helpers (monotone float <-> uint map)
__device__ __forceinline__ unsigned f2key(float x) {
    unsigned u = __float_as_uint(x);
    return u ^ ((unsigned)((int)u >> 31) | 0x80000000u);
}
__device__ __forceinline__ float key2f(unsigned k) {
    unsigned u = (k & 0x80000000u) ? (k ^ 0x80000000u) : ~k;
    return __uint_as_float(u);
}

// ---------------- fp32 GEMM: C(MxN) = A(MxK) @ B(KxN) ----------------
// 128x128 tile, 256 threads, 8x8 micro (vectorized B reads / C writes).
__global__ __launch_bounds__(256) void sgemm_kernel(
    const float* __restrict__ A, const float* __restrict__ Bm,
    float* __restrict__ C, int Mdim, int Ndim, int Kdim)
{
    __shared__ float As[128*33];   // [m][k] pad 33
    __shared__ float Bs[32*132];   // [k][n] pad 132
    int tid  = threadIdx.x;
    int brow = blockIdx.y * 128;
    int bcol = blockIdx.x * 128;
    int rowg = tid >> 4;             // 0..15
    int c0   = (tid & 15) * 4;       // 0..60
    float acc[8][8];
#pragma unroll
    for (int i = 0; i < 8; i++)
#pragma unroll
        for (int j = 0; j < 8; j++) acc[i][j] = 0.f;

    for (int kt = 0; kt < Kdim; kt += 32) {
#pragma unroll
        for (int i = 0; i < 4; i++) {
            int f4 = tid + i*256;
            int r = f4 >> 3, c4 = f4 & 7;
            float4 v = *(const float4*)(A + (size_t)(brow + r)*Kdim + kt + c4*4);
            As[r*33 + c4*4+0] = v.x; As[r*33 + c4*4+1] = v.y;
            As[r*33 + c4*4+2] = v.z; As[r*33 + c4*4+3] = v.w;
        }
#pragma unroll
        for (int i = 0; i < 4; i++) {
            int f4 = tid + i*256;
            int r = f4 >> 5, c4 = f4 & 31;
            *(float4*)&Bs[r*132 + c4*4] =
                *(const float4*)(Bm + (size_t)(kt + r)*Ndim + bcol + c4*4);
        }
        __syncthreads();
#pragma unroll 8
        for (int kk = 0; kk < 32; kk++) {
            float av[8];
#pragma unroll
            for (int i = 0; i < 8; i++) av[i] = As[(rowg + 16*i)*33 + kk];
            float4 b0 = *(float4*)&Bs[kk*132 + c0];
            float4 b1 = *(float4*)&Bs[kk*132 + 64 + c0];
#pragma unroll
            for (int i = 0; i < 8; i++) {
                acc[i][0] += av[i]*b0.x; acc[i][1] += av[i]*b0.y;
                acc[i][2] += av[i]*b0.z; acc[i][3] += av[i]*b0.w;
                acc[i][4] += av[i]*b1.x; acc[i][5] += av[i]*b1.y;
                acc[i][6] += av[i]*b1.z; acc[i][7] += av[i]*b1.w;
            }
        }
        __syncthreads();
    }
#pragma unroll
    for (int i = 0; i < 8; i++) {
        size_t r = (size_t)(brow + rowg + 16*i)*Ndim + bcol;
        *(float4*)(C + r + c0)      = make_float4(acc[i][0],acc[i][1],acc[i][2],acc[i][3]);
        *(float4*)(C + r + 64 + c0) = make_float4(acc[i][4],acc[i][5],acc[i][6],acc[i][7]);
    }
}

// ---------------- sequence-axis L2 norm of k,v columns ----------------
__global__ void colsq_kernel() {
    int b = blockIdx.x >> 4, chunk = blockIdx.x & 15;
    int j = threadIdx.x & 127, p = threadIdx.x >> 7;
    const float* base = g_kv + ((size_t)b*LL + chunk*128)*128;
    float ss = 0.f;
    for (int ll = p; ll < 128; ll += 2) {
        float v = base[ll*128 + j];
        ss += v*v;
    }
    __shared__ float sh[256];
    sh[threadIdx.x] = ss;
    __syncthreads();
    if (p == 0) g_part[(size_t)blockIdx.x*128 + j] = ss + sh[128 + j];
}

__global__ void normsum_kernel() {
    int tid = threadIdx.x;
    int b = tid >> 7, j = tid & 127;
    float s = 0.f;
    for (int c = 0; c < 16; c++) s += g_part[(b*16 + c)*128 + j];
    g_norm[tid] = s;
}

__global__ void normalize_kernel() {
    int idx = blockIdx.x*256 + threadIdx.x;
    int j  = idx & 127;
    int bl = idx >> 7;
    int b  = bl >> 11;
    float n = sqrtf(g_norm[b*128 + j]);
    n = fmaxf(n, 1e-12f);
    float v = g_kv[(size_t)idx] / n;
    if (j < 64) g_k[(size_t)bl*64 + j]        = v;
    else        g_v[(size_t)bl*64 + (j - 64)] = v;
}

// ---------------- sims = q @ k^T ----------------
// grid (mtile 16, ltile 16, z 32). 128x128 tile, K=64, 8x8 micro, vectorized.
__global__ __launch_bounds__(256) void sims_kernel() {
    extern __shared__ float sm[];
    float* Qs = sm;              // [128][65]  (l-rows x k)
    float* Kt = sm + 128*65;     // [64][132]  (k x m-rows, transposed)
    int z = blockIdx.z, b = z >> 4, h = z & 15;
    int lbase = blockIdx.y * 128, mbase = blockIdx.x * 128;
    const float* Aq = g_q + (size_t)b*LL*DD + h*DH;
    const float* Bk = g_k + (size_t)b*LL*DH;
    float* Cs = g_sims + (size_t)z*LL*LL;
    int tid = threadIdx.x;
#pragma unroll
    for (int i = 0; i < 8; i++) {            // Q tile 128x64
        int f4 = tid + i*256;
        int r = f4 >> 4, c4 = f4 & 15;
        float4 v = *(const float4*)(Aq + (size_t)(lbase + r)*DD + c4*4);
        Qs[r*65 + c4*4+0] = v.x; Qs[r*65 + c4*4+1] = v.y;
        Qs[r*65 + c4*4+2] = v.z; Qs[r*65 + c4*4+3] = v.w;
    }
#pragma unroll
    for (int i = 0; i < 8; i++) {            // K tile 128x64 -> transposed
        int f4 = tid + i*256;
        int lo = f4 & 31, hi = f4 >> 5;
        int r  = (lo & 7) + 8*(hi & 15);     // 0..127
        int c4 = (lo >> 3) + 4*(hi >> 4);    // 0..15
        float4 v = *(const float4*)(Bk + (size_t)(mbase + r)*DH + c4*4);
        Kt[(c4*4+0)*132 + r] = v.x; Kt[(c4*4+1)*132 + r] = v.y;
        Kt[(c4*4+2)*132 + r] = v.z; Kt[(c4*4+3)*132 + r] = v.w;
    }
    __syncthreads();
    int rowg = tid >> 4, c0 = (tid & 15)*4;
    float acc[8][8];
#pragma unroll
    for (int i = 0; i < 8; i++)
#pragma unroll
        for (int j = 0; j < 8; j++) acc[i][j] = 0.f;
#pragma unroll 8
    for (int kk = 0; kk < 64; kk++) {
        float av[8];
#pragma unroll
        for (int i = 0; i < 8; i++) av[i] = Qs[(rowg + 16*i)*65 + kk];
        float4 b0 = *(float4*)&Kt[kk*132 + c0];
        float4 b1 = *(float4*)&Kt[kk*132 + 64 + c0];
#pragma unroll
        for (int i = 0; i < 8; i++) {
            acc[i][0] += av[i]*b0.x; acc[i][1] += av[i]*b0.y;
            acc[i][2] += av[i]*b0.z; acc[i][3] += av[i]*b0.w;
            acc[i][4] += av[i]*b1.x; acc[i][5] += av[i]*b1.y;
            acc[i][6] += av[i]*b1.z; acc[i][7] += av[i]*b1.w;
        }
    }
#pragma unroll
    for (int i = 0; i < 8; i++) {
        size_t off = (size_t)(lbase + rowg + 16*i)*LL + mbase;
        *(float4*)(Cs + off + c0)      = make_float4(acc[i][0],acc[i][1],acc[i][2],acc[i][3]);
        *(float4*)(Cs + off + 64 + c0) = make_float4(acc[i][4],acc[i][5],acc[i][6],acc[i][7]);
    }
}

// ---------------- per-row: max + exact top-32 (NO exp here anymore) ---------
__global__ __launch_bounds__(256) void stats_topk_kernel() {  // grid 65536
    __shared__ unsigned cand_key[256];
    __shared__ int      cand_idx[256];
    __shared__ unsigned redk[8];
    size_t row = blockIdx.x;
    const float* S = g_sims + row * LL;
    int tid = threadIdx.x, lane = tid & 31, wid = tid >> 5;

    float4 a = ((const float4*)S)[tid];
    float4 c = ((const float4*)S)[tid + 256];
    float v[8] = {a.x, a.y, a.z, a.w, c.x, c.y, c.z, c.w};
    unsigned key[8];
#pragma unroll
    for (int j = 0; j < 8; j++) key[j] = f2key(v[j]);

    // row max via redux on keys
    unsigned km = key[0];
#pragma unroll
    for (int j = 1; j < 8; j++) km = max(km, key[j]);
    km = __reduce_max_sync(0xffffffffu, km);
    if (lane == 0) redk[wid] = km;
    __syncthreads();
    if (tid == 0) {
        unsigned m = redk[0];
        for (int w = 1; w < 8; w++) m = max(m, redk[w]);
        g_rowmax[row] = key2f(m);
    }

    // per-warp top-32 of its 256 elements (cached local max, redux argmax)
    unsigned lk = 0; int lj = 0;
#pragma unroll
    for (int j = 0; j < 8; j++) if (key[j] > lk) { lk = key[j]; lj = j; }
    for (int it = 0; it < TK; it++) {
        unsigned w = __reduce_max_sync(0xffffffffu, lk);
        unsigned ball = __ballot_sync(0xffffffffu, lk == w);
        int src = __ffs(ball) - 1;
        if (lane == src) {
            cand_key[wid*32 + it] = w;
            cand_idx[wid*32 + it] = (lj < 4) ? (4*tid + lj) : (1024 + 4*tid + lj - 4);
            key[lj] = 0u;
            lk = 0; lj = 0;
#pragma unroll
            for (int j = 0; j < 8; j++) if (key[j] > lk) { lk = key[j]; lj = j; }
        }
    }
    __syncthreads();

    // warp 0 merges 256 candidates -> global top-32 (sorted desc)
    if (wid == 0) {
        unsigned mkey[8]; int midx[8];
#pragma unroll
        for (int j = 0; j < 8; j++) {
            mkey[j] = cand_key[lane*8 + j];
            midx[j] = cand_idx[lane*8 + j];
        }
        unsigned mk = 0; int mj = 0;
#pragma unroll
        for (int j = 0; j < 8; j++) if (mkey[j] > mk) { mk = mkey[j]; mj = j; }
        for (int it = 0; it < TK; it++) {
            unsigned w = __reduce_max_sync(0xffffffffu, mk);
            unsigned ball = __ballot_sync(0xffffffffu, mk == w);
            int src = __ffs(ball) - 1;
            if (lane == src) {
                g_topv[row*TK + it] = key2f(w);
                g_topi[row*TK + it] = midx[mj];
                mkey[mj] = 0u;
                mk = 0; mj = 0;
#pragma unroll
                for (int j = 0; j < 8; j++) if (mkey[j] > mk) { mk = mkey[j]; mj = j; }
            }
        }
    }
}

// ---------------- local = (sum_m e_m v_m)/(sum_m e_m), flash-normalized -----
// grid (ltile 8, z 32). 256 rows x 64 cols, K-tiles of 64, 16x4 micro.
// Per-thread slot structure: i=0..15, f4=tid+256i -> r = (tid&7)+8*(tid>>5)+64*(i&3),
// c4 = ((tid>>3)&3)+4*(i>>2). Thread owns 4 fixed rows (ii=i&3) across the stream.
__global__ __launch_bounds__(256) void pv_kernel() {
    extern __shared__ float sm[];
    float* Pt   = sm;                 // [64][260]  (m x l-rows, transposed, exp'd)
    float* Vs   = sm + 64*260;        // [64][68]
    float* smx  = Vs + 64*68;         // [256] rowmax
    float* part = smx + 256;          // [4][256] per-thread rowsum partials
    float* rsin = part + 1024;        // [256] 1/rowsum
    int z = blockIdx.y, b = z >> 4, h = z & 15;
    int lbase = blockIdx.x * 256;
    const float* S = g_sims + (size_t)z*LL*LL;
    int tid = threadIdx.x;
    smx[tid] = g_rowmax[(size_t)z*LL + lbase + tid];
    __syncthreads();
    int rowg4 = (tid >> 4)*4;        // 0..60
    int c0    = (tid & 15)*4;        // 0..60
    float acc[16][4];
#pragma unroll
    for (int i = 0; i < 16; i++)
#pragma unroll
        for (int j = 0; j < 4; j++) acc[i][j] = 0.f;
    float psum[4] = {0.f, 0.f, 0.f, 0.f};

    for (int mt = 0; mt < LL; mt += 64) {
        // S tile 256x64 -> exp (unnormalized) -> transposed into Pt
#pragma unroll
        for (int i = 0; i < 16; i++) {
            int f4 = tid + i*256;
            int r  = (f4 & 7) + 8*((f4 >> 5) & 31);    // 0..255
            int c4 = ((f4 >> 3) & 3) + 4*(f4 >> 10);   // 0..15
            float4 v = *(const float4*)(S + (size_t)(lbase + r)*LL + mt + c4*4);
            float m = smx[r];
            float e0 = __expf((v.x - m)*SCALE);
            float e1 = __expf((v.y - m)*SCALE);
            float e2 = __expf((v.z - m)*SCALE);
            float e3 = __expf((v.w - m)*SCALE);
            Pt[(c4*4+0)*260 + r] = e0;
            Pt[(c4*4+1)*260 + r] = e1;
            Pt[(c4*4+2)*260 + r] = e2;
            Pt[(c4*4+3)*260 + r] = e3;
            psum[i & 3] += (e0 + e1) + (e2 + e3);
        }
        // V tile 64x64
#pragma unroll
        for (int i = 0; i < 4; i++) {
            int f4 = tid + i*256;
            int r = f4 >> 4, c4 = f4 & 15;
            *(float4*)&Vs[r*68 + c4*4] =
                *(const float4*)(g_v + ((size_t)b*LL + mt + r)*DH + c4*4);
        }
        __syncthreads();
#pragma unroll 8
        for (int ml = 0; ml < 64; ml++) {
            float4 a0 = *(float4*)&Pt[ml*260 + rowg4];
            float4 a1 = *(float4*)&Pt[ml*260 + 64  + rowg4];
            float4 a2 = *(float4*)&Pt[ml*260 + 128 + rowg4];
            float4 a3 = *(float4*)&Pt[ml*260 + 192 + rowg4];
            float4 bv = *(float4*)&Vs[ml*68 + c0];
            float aq[16] = {a0.x,a0.y,a0.z,a0.w, a1.x,a1.y,a1.z,a1.w,
                            a2.x,a2.y,a2.z,a2.w, a3.x,a3.y,a3.z,a3.w};
#pragma unroll
            for (int i = 0; i < 16; i++) {
                acc[i][0] += aq[i]*bv.x; acc[i][1] += aq[i]*bv.y;
                acc[i][2] += aq[i]*bv.z; acc[i][3] += aq[i]*bv.w;
            }
        }
        __syncthreads();
    }

    // deterministic rowsum reduction: part[ii][tid] -> rs[row] (4 contributors)
#pragma unroll
    for (int ii = 0; ii < 4; ii++) part[ii*256 + tid] = psum[ii];
    __syncthreads();
    {
        int rho = tid;                         // row within block
        int ii  = rho >> 6;
        float s = 0.f;
#pragma unroll
        for (int k = 0; k < 4; k++) {
            int t = (rho & 7) | (k << 3) | (((rho >> 3) & 7) << 5);
            s += part[ii*256 + t];
        }
        rsin[rho] = 1.0f / s;
    }
    __syncthreads();

#pragma unroll
    for (int q = 0; q < 4; q++)
#pragma unroll
        for (int i = 0; i < 4; i++) {
            int rl = q*64 + rowg4 + i;
            float inv = rsin[rl];
            int r = lbase + rl;
            *(float4*)(g_attn + ((size_t)b*LL + r)*DD + h*DH + c0) =
                make_float4(acc[q*4+i][0]*inv, acc[q*4+i][1]*inv,
                            acc[q*4+i][2]*inv, acc[q*4+i][3]*inv);
        }
}

// ---------------- retrieved = softmax(topv*scale) @ k[topi] ----------------
__global__ __launch_bounds__(256) void retrieved_kernel() {
    __shared__ float ps[8][32];
    __shared__ int   tis[8][32];
    int wid = threadIdx.x >> 5, lane = threadIdx.x & 31;
    size_t row = (size_t)blockIdx.x*8 + wid;
    int z = (int)(row >> 11), l = (int)(row & 2047);
    int b = z >> 4, h = z & 15;
    float tv = g_topv[row*TK + lane];
    int   ti = g_topi[row*TK + lane];
    float mx = __shfl_sync(0xffffffffu, tv, 0);   // topv sorted desc
    float p = __expf((tv - mx)*SCALE);
    float psum = p;
#pragma unroll
    for (int o = 16; o; o >>= 1) psum += __shfl_xor_sync(0xffffffffu, psum, o);
    ps[wid][lane] = p / psum;
    tis[wid][lane] = ti;
    __syncwarp();
    const float* kb = g_k + (size_t)b*LL*DH;
    float a0 = 0.f, a1 = 0.f;
#pragma unroll 8
    for (int t = 0; t < TK; t++) {
        float w = ps[wid][t];
        const float* kr = kb + (size_t)tis[wid][t]*DH;
        a0 += w * kr[lane];
        a1 += w * kr[lane + 32];
    }
    size_t off = ((size_t)b*LL + l)*DD + h*DH;
    g_attn[off + lane]      += a0;
    g_attn[off + lane + 32] += a1;
}

// ---------------- launch ----------------
extern "C" void kernel_launch(void* const* d_in, const int* in_sizes, int n_in,
                              void* d_out, int out_size)
{
    const float* q_in     = (const float*)d_in[0];
    const float* kv_in    = (const float*)d_in[1];
    const float* w_q      = (const float*)d_in[2];
    const float* w_kv     = (const float*)d_in[3];
    const float* w_concat = (const float*)d_in[4];
    float* out = (float*)d_out;

    float *p_q, *p_kv, *p_attn;
    cudaGetSymbolAddress((void**)&p_q,    g_q);
    cudaGetSymbolAddress((void**)&p_kv,   g_kv);
    cudaGetSymbolAddress((void**)&p_attn, g_attn);

    static const int SIMS_SMEM = (128*65 + 64*132)*4;                     // 67072
    static const int PV_SMEM   = (64*260 + 64*68 + 256 + 1024 + 256)*4;   // 90112
    cudaFuncSetAttribute(sims_kernel, cudaFuncAttributeMaxDynamicSharedMemorySize, SIMS_SMEM);
    cudaFuncSetAttribute(pv_kernel,   cudaFuncAttributeMaxDynamicSharedMemorySize, PV_SMEM);

    // 1. q = q_in @ w_q   (4096x1024x1024)
    sgemm_kernel<<<dim3(8, 32), 256>>>(q_in, w_q, p_q, BB*LL, DD, DD);
    // 2. kv = kv_in @ w_kv (4096x128x1024)
    sgemm_kernel<<<dim3(1, 32), 256>>>(kv_in, w_kv, p_kv, BB*LL, 2*DH, DD);
    // 3. l2 norm over sequence axis
    colsq_kernel<<<32, 256>>>();
    normsum_kernel<<<1, 256>>>();
    normalize_kernel<<<2048, 256>>>();
    // 4. sims (fp32 SIMT — selection-faithful)
    sims_kernel<<<dim3(16, 16, 32), 256, SIMS_SMEM>>>();
    // 5. row max + exact top-32 (no exp pass anymore)
    stats_topk_kernel<<<BB*HH*LL, 256>>>();
    // 6. local attention (flash-normalized P@V) -> g_attn
    pv_kernel<<<dim3(8, 32), 256, PV_SMEM>>>();
    // 7. retrieved (+= into g_attn)
    retrieved_kernel<<<BB*HH*LL/8, 256>>>();
    // 8. out = attn @ w_concat
    sgemm_kernel<<<dim3(8, 32), 256>>>(p_attn, w_concat, out, BB*LL, DD, DD);
}

// round 14
// speedup vs baseline: 1.8197x; 1.0318x over previous
#include <cuda_runtime.h>
#include <math.h>

#define BB 2
#define LL 2048
#define DD 1024
#define HH 16
#define DH 64
#define TK 32
#define SCALE 0.125f   // 1/sqrt(64)

// ---------------- scratch (device globals; no allocs allowed) ----------------
__device__ float g_q   [(size_t)BB*LL*DD];
__device__ float g_kv  [(size_t)BB*LL*2*DH];
__device__ float g_k   [(size_t)BB*LL*DH];
__device__ float g_v   [(size_t)BB*LL*DH];
__device__ float g_part[BB*16*128];
__device__ float g_sims[(size_t)BB*HH*LL*LL];       // 512 MB
__device__ float g_rowmax[BB*HH*LL];
__device__ float g_topv[(size_t)BB*HH*LL*TK];
__device__ int   g_topi[(size_t)BB*HH*LL*TK];
__device__ float g_attn[(size_t)BB*LL*DD];

// ordered-uint key helpers (monotone float <-> uint map)
__device__ __forceinline__ unsigned f2key(float x) {
    unsigned u = __float_as_uint(x);
    return u ^ ((unsigned)((int)u >> 31) | 0x80000000u);
}
__device__ __forceinline__ float key2f(unsigned k) {
    unsigned u = (k & 0x80000000u) ? (k ^ 0x80000000u) : ~k;
    return __uint_as_float(u);
}

// ---------------- fp32 GEMM body: C(MxN) = A(MxK) @ B(KxN) ----------------
// 128x128 tile, 256 threads, 8x8 micro, float4 av loads (kk unrolled by 4).
// Accumulation per acc element is kk-sequential ascending -> bitwise-stable.
__device__ __forceinline__ void sgemm_body(
    const float* __restrict__ A, const float* __restrict__ Bm,
    float* __restrict__ C, int Ndim, int Kdim, int brow, int bcol)
{
    __shared__ float As[128*36];   // [m][k] pad 36 (16B-aligned kk groups)
    __shared__ float Bs[32*132];   // [k][n] pad 132
    int tid  = threadIdx.x;
    int rowg = tid >> 4;             // 0..15
    int c0   = (tid & 15) * 4;       // 0..60
    float acc[8][8];
#pragma unroll
    for (int i = 0; i < 8; i++)
#pragma unroll
        for (int j = 0; j < 8; j++) acc[i][j] = 0.f;

    for (int kt = 0; kt < Kdim; kt += 32) {
#pragma unroll
        for (int i = 0; i < 4; i++) {
            int f4 = tid + i*256;
            int r = f4 >> 3, c4 = f4 & 7;
            float4 v = *(const float4*)(A + (size_t)(brow + r)*Kdim + kt + c4*4);
            *(float4*)&As[r*36 + c4*4] = v;
        }
#pragma unroll
        for (int i = 0; i < 4; i++) {
            int f4 = tid + i*256;
            int r = f4 >> 5, c4 = f4 & 31;
            *(float4*)&Bs[r*132 + c4*4] =
                *(const float4*)(Bm + (size_t)(kt + r)*Ndim + bcol + c4*4);
        }
        __syncthreads();
#pragma unroll
        for (int k4 = 0; k4 < 8; k4++) {
            float4 a4[8];
#pragma unroll
            for (int i = 0; i < 8; i++)
                a4[i] = *(float4*)&As[(rowg + 16*i)*36 + k4*4];
#pragma unroll
            for (int j = 0; j < 4; j++) {
                int kk = k4*4 + j;
                float4 b0 = *(float4*)&Bs[kk*132 + c0];
                float4 b1 = *(float4*)&Bs[kk*132 + 64 + c0];
#pragma unroll
                for (int i = 0; i < 8; i++) {
                    float av = (j == 0) ? a4[i].x : (j == 1) ? a4[i].y
                             : (j == 2) ? a4[i].z : a4[i].w;
                    acc[i][0] += av*b0.x; acc[i][1] += av*b0.y;
                    acc[i][2] += av*b0.z; acc[i][3] += av*b0.w;
                    acc[i][4] += av*b1.x; acc[i][5] += av*b1.y;
                    acc[i][6] += av*b1.z; acc[i][7] += av*b1.w;
                }
            }
        }
        __syncthreads();
    }
#pragma unroll
    for (int i = 0; i < 8; i++) {
        size_t r = (size_t)(brow + rowg + 16*i)*Ndim + bcol;
        *(float4*)(C + r + c0)      = make_float4(acc[i][0],acc[i][1],acc[i][2],acc[i][3]);
        *(float4*)(C + r + 64 + c0) = make_float4(acc[i][4],acc[i][5],acc[i][6],acc[i][7]);
    }
}

// z=0: A0@B0 -> C0 (N0 cols). z=1: A1@B1 -> C1 (128 cols, blockIdx.x==0 only).
__global__ __launch_bounds__(256) void sgemm2_kernel(
    const float* __restrict__ A0, const float* __restrict__ B0, float* __restrict__ C0,
    const float* __restrict__ A1, const float* __restrict__ B1, float* __restrict__ C1,
    int N0, int Kdim)
{
    if (blockIdx.z == 0) {
        sgemm_body(A0, B0, C0, N0, Kdim, blockIdx.y*128, blockIdx.x*128);
    } else {
        if (blockIdx.x != 0) return;
        sgemm_body(A1, B1, C1, 128, Kdim, blockIdx.y*128, 0);
    }
}

// ---------------- sequence-axis L2 norm of k,v columns ----------------
__global__ void colsq_kernel() {
    int b = blockIdx.x >> 4, chunk = blockIdx.x & 15;
    int j = threadIdx.x & 127, p = threadIdx.x >> 7;
    const float* base = g_kv + ((size_t)b*LL + chunk*128)*128;
    float ss = 0.f;
    for (int ll = p; ll < 128; ll += 2) {
        float v = base[ll*128 + j];
        ss += v*v;
    }
    __shared__ float sh[256];
    sh[threadIdx.x] = ss;
    __syncthreads();
    if (p == 0) g_part[(size_t)blockIdx.x*128 + j] = ss + sh[128 + j];
}

// normsum folded in: every thread re-sums its column's 16 partials (L2-hot),
// same c=0..15 order as before -> bitwise-identical norms.
__global__ void normalize_kernel() {  // grid 2048, 256 thr
    int idx = blockIdx.x*256 + threadIdx.x;
    int j  = idx & 127;
    int bl = idx >> 7;
    int b  = bl >> 11;
    float s = 0.f;
#pragma unroll
    for (int c = 0; c < 16; c++) s += g_part[(b*16 + c)*128 + j];
    float n = sqrtf(s);
    n = fmaxf(n, 1e-12f);
    float v = g_kv[(size_t)idx] / n;
    if (j < 64) g_k[(size_t)bl*64 + j]        = v;
    else        g_v[(size_t)bl*64 + (j - 64)] = v;
}

// ---------------- sims = q @ k^T ----------------
// grid (mtile 16, ltile 16, z 32). 128x128 tile, K=64, 8x8 micro, av float4.
__global__ __launch_bounds__(256) void sims_kernel() {
    extern __shared__ float sm[];
    float* Qs = sm;              // [128][68]  (l-rows x k, pad 68 for float4 kk)
    float* Kt = sm + 128*68;     // [64][132]  (k x m-rows, transposed)
    int z = blockIdx.z, b = z >> 4, h = z & 15;
    int lbase = blockIdx.y * 128, mbase = blockIdx.x * 128;
    const float* Aq = g_q + (size_t)b*LL*DD + h*DH;
    const float* Bk = g_k + (size_t)b*LL*DH;
    float* Cs = g_sims + (size_t)z*LL*LL;
    int tid = threadIdx.x;
#pragma unroll
    for (int i = 0; i < 8; i++) {            // Q tile 128x64
        int f4 = tid + i*256;
        int r = f4 >> 4, c4 = f4 & 15;
        float4 v = *(const float4*)(Aq + (size_t)(lbase + r)*DD + c4*4);
        *(float4*)&Qs[r*68 + c4*4] = v;
    }
#pragma unroll
    for (int i = 0; i < 8; i++) {            // K tile 128x64 -> transposed
        int f4 = tid + i*256;
        int lo = f4 & 31, hi = f4 >> 5;
        int r  = (lo & 7) + 8*(hi & 15);     // 0..127
        int c4 = (lo >> 3) + 4*(hi >> 4);    // 0..15
        float4 v = *(const float4*)(Bk + (size_t)(mbase + r)*DH + c4*4);
        Kt[(c4*4+0)*132 + r] = v.x; Kt[(c4*4+1)*132 + r] = v.y;
        Kt[(c4*4+2)*132 + r] = v.z; Kt[(c4*4+3)*132 + r] = v.w;
    }
    __syncthreads();
    int rowg = tid >> 4, c0 = (tid & 15)*4;
    float acc[8][8];
#pragma unroll
    for (int i = 0; i < 8; i++)
#pragma unroll
        for (int j = 0; j < 8; j++) acc[i][j] = 0.f;
#pragma unroll
    for (int k4 = 0; k4 < 16; k4++) {
        float4 a4[8];
#pragma unroll
        for (int i = 0; i < 8; i++)
            a4[i] = *(float4*)&Qs[(rowg + 16*i)*68 + k4*4];
#pragma unroll
        for (int j = 0; j < 4; j++) {
            int kk = k4*4 + j;
            float4 b0 = *(float4*)&Kt[kk*132 + c0];
            float4 b1 = *(float4*)&Kt[kk*132 + 64 + c0];
#pragma unroll
            for (int i = 0; i < 8; i++) {
                float av = (j == 0) ? a4[i].x : (j == 1) ? a4[i].y
                         : (j == 2) ? a4[i].z : a4[i].w;
                acc[i][0] += av*b0.x; acc[i][1] += av*b0.y;
                acc[i][2] += av*b0.z; acc[i][3] += av*b0.w;
                acc[i][4] += av*b1.x; acc[i][5] += av*b1.y;
                acc[i][6] += av*b1.z; acc[i][7] += av*b1.w;
            }
        }
    }
#pragma unroll
    for (int i = 0; i < 8; i++) {
        size_t off = (size_t)(lbase + rowg + 16*i)*LL + mbase;
        *(float4*)(Cs + off + c0)      = make_float4(acc[i][0],acc[i][1],acc[i][2],acc[i][3]);
        *(float4*)(Cs + off + 64 + c0) = make_float4(acc[i][4],acc[i][5],acc[i][6],acc[i][7]);
    }
}

// ---------------- per-row: max + exact top-32 ----------------
__global__ __launch_bounds__(256) void stats_topk_kernel() {  // grid 65536
    __shared__ unsigned cand_key[256];
    __shared__ int      cand_idx[256];
    __shared__ unsigned redk[8];
    size_t row = blockIdx.x;
    const float* S = g_sims + row * LL;
    int tid = threadIdx.x, lane = tid & 31, wid = tid >> 5;

    float4 a = ((const float4*)S)[tid];
    float4 c = ((const float4*)S)[tid + 256];
    float v[8] = {a.x, a.y, a.z, a.w, c.x, c.y, c.z, c.w};
    unsigned key[8];
#pragma unroll
    for (int j = 0; j < 8; j++) key[j] = f2key(v[j]);

    unsigned km = key[0];
#pragma unroll
    for (int j = 1; j < 8; j++) km = max(km, key[j]);
    km = __reduce_max_sync(0xffffffffu, km);
    if (lane == 0) redk[wid] = km;
    __syncthreads();
    if (tid == 0) {
        unsigned m = redk[0];
        for (int w = 1; w < 8; w++) m = max(m, redk[w]);
        g_rowmax[row] = key2f(m);
    }

    unsigned lk = 0; int lj = 0;
#pragma unroll
    for (int j = 0; j < 8; j++) if (key[j] > lk) { lk = key[j]; lj = j; }
    for (int it = 0; it < TK; it++) {
        unsigned w = __reduce_max_sync(0xffffffffu, lk);
        unsigned ball = __ballot_sync(0xffffffffu, lk == w);
        int src = __ffs(ball) - 1;
        if (lane == src) {
            cand_key[wid*32 + it] = w;
            cand_idx[wid*32 + it] = (lj < 4) ? (4*tid + lj) : (1024 + 4*tid + lj - 4);
            key[lj] = 0u;
            lk = 0; lj = 0;
#pragma unroll
            for (int j = 0; j < 8; j++) if (key[j] > lk) { lk = key[j]; lj = j; }
        }
    }
    __syncthreads();

    if (wid == 0) {
        unsigned mkey[8]; int midx[8];
#pragma unroll
        for (int j = 0; j < 8; j++) {
            mkey[j] = cand_key[lane*8 + j];
            midx[j] = cand_idx[lane*8 + j];
        }
        unsigned mk = 0; int mj = 0;
#pragma unroll
        for (int j = 0; j < 8; j++) if (mkey[j] > mk) { mk = mkey[j]; mj = j; }
        for (int it = 0; it < TK; it++) {
            unsigned w = __reduce_max_sync(0xffffffffu, mk);
            unsigned ball = __ballot_sync(0xffffffffu, mk == w);
            int src = __ffs(ball) - 1;
            if (lane == src) {
                g_topv[row*TK + it] = key2f(w);
                g_topi[row*TK + it] = midx[mj];
                mkey[mj] = 0u;
                mk = 0; mj = 0;
#pragma unroll
                for (int j = 0; j < 8; j++) if (mkey[j] > mk) { mk = mkey[j]; mj = j; }
            }
        }
    }
}

// ---------------- local = (sum_m e_m v_m)/(sum_m e_m), flash-normalized -----
__global__ __launch_bounds__(256) void pv_kernel() {
    extern __shared__ float sm[];
    float* Pt   = sm;                 // [64][260]
    float* Vs   = sm + 64*260;        // [64][68]
    float* smx  = Vs + 64*68;         // [256] rowmax
    float* part = smx + 256;          // [4][256] rowsum partials
    float* rsin = part + 1024;        // [256] 1/rowsum
    int z = blockIdx.y, b = z >> 4, h = z & 15;
    int lbase = blockIdx.x * 256;
    const float* S = g_sims + (size_t)z*LL*LL;
    int tid = threadIdx.x;
    smx[tid] = g_rowmax[(size_t)z*LL + lbase + tid];
    __syncthreads();
    int rowg4 = (tid >> 4)*4;
    int c0    = (tid & 15)*4;
    float acc[16][4];
#pragma unroll
    for (int i = 0; i < 16; i++)
#pragma unroll
        for (int j = 0; j < 4; j++) acc[i][j] = 0.f;
    float psum[4] = {0.f, 0.f, 0.f, 0.f};

    for (int mt = 0; mt < LL; mt += 64) {
#pragma unroll
        for (int i = 0; i < 16; i++) {
            int f4 = tid + i*256;
            int r  = (f4 & 7) + 8*((f4 >> 5) & 31);
            int c4 = ((f4 >> 3) & 3) + 4*(f4 >> 10);
            float4 v = *(const float4*)(S + (size_t)(lbase + r)*LL + mt + c4*4);
            float m = smx[r];
            float e0 = __expf((v.x - m)*SCALE);
            float e1 = __expf((v.y - m)*SCALE);
            float e2 = __expf((v.z - m)*SCALE);
            float e3 = __expf((v.w - m)*SCALE);
            Pt[(c4*4+0)*260 + r] = e0;
            Pt[(c4*4+1)*260 + r] = e1;
            Pt[(c4*4+2)*260 + r] = e2;
            Pt[(c4*4+3)*260 + r] = e3;
            psum[i & 3] += (e0 + e1) + (e2 + e3);
        }
#pragma unroll
        for (int i = 0; i < 4; i++) {
            int f4 = tid + i*256;
            int r = f4 >> 4, c4 = f4 & 15;
            *(float4*)&Vs[r*68 + c4*4] =
                *(const float4*)(g_v + ((size_t)b*LL + mt + r)*DH + c4*4);
        }
        __syncthreads();
#pragma unroll 8
        for (int ml = 0; ml < 64; ml++) {
            float4 a0 = *(float4*)&Pt[ml*260 + rowg4];
            float4 a1 = *(float4*)&Pt[ml*260 + 64  + rowg4];
            float4 a2 = *(float4*)&Pt[ml*260 + 128 + rowg4];
            float4 a3 = *(float4*)&Pt[ml*260 + 192 + rowg4];
            float4 bv = *(float4*)&Vs[ml*68 + c0];
            float aq[16] = {a0.x,a0.y,a0.z,a0.w, a1.x,a1.y,a1.z,a1.w,
                            a2.x,a2.y,a2.z,a2.w, a3.x,a3.y,a3.z,a3.w};
#pragma unroll
            for (int i = 0; i < 16; i++) {
                acc[i][0] += aq[i]*bv.x; acc[i][1] += aq[i]*bv.y;
                acc[i][2] += aq[i]*bv.z; acc[i][3] += aq[i]*bv.w;
            }
        }
        __syncthreads();
    }

#pragma unroll
    for (int ii = 0; ii < 4; ii++) part[ii*256 + tid] = psum[ii];
    __syncthreads();
    {
        int rho = tid;
        int ii  = rho >> 6;
        float s = 0.f;
#pragma unroll
        for (int k = 0; k < 4; k++) {
            int t = (rho & 7) | (k << 3) | (((rho >> 3) & 7) << 5);
            s += part[ii*256 + t];
        }
        rsin[rho] = 1.0f / s;
    }
    __syncthreads();

#pragma unroll
    for (int q = 0; q < 4; q++)
#pragma unroll
        for (int i = 0; i < 4; i++) {
            int rl = q*64 + rowg4 + i;
            float inv = rsin[rl];
            int r = lbase + rl;
            *(float4*)(g_attn + ((size_t)b*LL + r)*DD + h*DH + c0) =
                make_float4(acc[q*4+i][0]*inv, acc[q*4+i][1]*inv,
                            acc[q*4+i][2]*inv, acc[q*4+i][3]*inv);
        }
}

// ---------------- retrieved = softmax(topv*scale) @ k[topi] ----------------
__global__ __launch_bounds__(256) void retrieved_kernel() {
    __shared__ float ps[8][32];
    __shared__ int   tis[8][32];
    int wid = threadIdx.x >> 5, lane = threadIdx.x & 31;
    size_t row = (size_t)blockIdx.x*8 + wid;
    int z = (int)(row >> 11), l = (int)(row & 2047);
    int b = z >> 4, h = z & 15;
    float tv = g_topv[row*TK + lane];
    int   ti = g_topi[row*TK + lane];
    float mx = __shfl_sync(0xffffffffu, tv, 0);
    float p = __expf((tv - mx)*SCALE);
    float psum = p;
#pragma unroll
    for (int o = 16; o; o >>= 1) psum += __shfl_xor_sync(0xffffffffu, psum, o);
    ps[wid][lane] = p / psum;
    tis[wid][lane] = ti;
    __syncwarp();
    const float* kb = g_k + (size_t)b*LL*DH;
    float a0 = 0.f, a1 = 0.f;
#pragma unroll 8
    for (int t = 0; t < TK; t++) {
        float w = ps[wid][t];
        const float* kr = kb + (size_t)tis[wid][t]*DH;
        a0 += w * kr[lane];
        a1 += w * kr[lane + 32];
    }
    size_t off = ((size_t)b*LL + l)*DD + h*DH;
    g_attn[off + lane]      += a0;
    g_attn[off + lane + 32] += a1;
}

// ---------------- launch ----------------
extern "C" void kernel_launch(void* const* d_in, const int* in_sizes, int n_in,
                              void* d_out, int out_size)
{
    const float* q_in     = (const float*)d_in[0];
    const float* kv_in    = (const float*)d_in[1];
    const float* w_q      = (const float*)d_in[2];
    const float* w_kv     = (const float*)d_in[3];
    const float* w_concat = (const float*)d_in[4];
    float* out = (float*)d_out;

    float *p_q, *p_kv, *p_attn;
    cudaGetSymbolAddress((void**)&p_q,    g_q);
    cudaGetSymbolAddress((void**)&p_kv,   g_kv);
    cudaGetSymbolAddress((void**)&p_attn, g_attn);

    static const int SIMS_SMEM = (128*68 + 64*132)*4;                     // 68608
    static const int PV_SMEM   = (64*260 + 64*68 + 256 + 1024 + 256)*4;   // 90112
    cudaFuncSetAttribute(sims_kernel, cudaFuncAttributeMaxDynamicSharedMemorySize, SIMS_SMEM);
    cudaFuncSetAttribute(pv_kernel,   cudaFuncAttributeMaxDynamicSharedMemorySize, PV_SMEM);

    // 1. q = q_in @ w_q (z=0) and kv = kv_in @ w_kv (z=1), one launch
    sgemm2_kernel<<<dim3(8, 32, 2), 256>>>(q_in, w_q, p_q, kv_in, w_kv, p_kv, DD, DD);
    // 2-3. l2 norm over sequence axis (normsum folded into normalize)
    colsq_kernel<<<32, 256>>>();
    normalize_kernel<<<2048, 256>>>();
    // 4. sims (fp32 SIMT, vectorized av) — ncu capture slot
    sims_kernel<<<dim3(16, 16, 32), 256, SIMS_SMEM>>>();
    // 5. row max + exact top-32
    stats_topk_kernel<<<BB*HH*LL, 256>>>();
    // 6. local attention (flash-normalized P@V) -> g_attn
    pv_kernel<<<dim3(8, 32), 256, PV_SMEM>>>();
    // 7. retrieved (+= into g_attn)
    retrieved_kernel<<<BB*HH*LL/8, 256>>>();
    // 8. out = attn @ w_concat
    sgemm2_kernel<<<dim3(8, 32, 1), 256>>>(p_attn, w_concat, out, p_attn, w_concat, out, DD, DD);
}

// round 15
// speedup vs baseline: 1.9210x; 1.0557x over previous
#include <cuda_runtime.h>
#include <math.h>
#include <stdint.h>

#define BB 2
#define LL 2048
#define DD 1024
#define HH 16
#define DH 64
#define TK 32
#define SCALE 0.125f   // 1/sqrt(64)

// ---------------- scratch (device globals; no allocs allowed) ----------------
__device__ float g_q   [(size_t)BB*LL*DD];
__device__ float g_kv  [(size_t)BB*LL*2*DH];
__device__ float g_k   [(size_t)BB*LL*DH];
__device__ float g_v   [(size_t)BB*LL*DH];
__device__ float g_part[BB*16*128];
__device__ float g_sims[(size_t)BB*HH*LL*LL];       // 512 MB
__device__ float g_rowmax[BB*HH*LL];
__device__ float g_topv[(size_t)BB*HH*LL*TK];
__device__ int   g_topi[(size_t)BB*HH*LL*TK];
__device__ float g_attn[(size_t)BB*LL*DD];

// ordered-uint key helpers (monotone float <-> uint map)
__device__ __forceinline__ unsigned f2key(float x) {
    unsigned u = __float_as_uint(x);
    return u ^ ((unsigned)((int)u >> 31) | 0x80000000u);
}
__device__ __forceinline__ float key2f(unsigned k) {
    unsigned u = (k & 0x80000000u) ? (k ^ 0x80000000u) : ~k;
    return __uint_as_float(u);
}

// ---------------- packed f32x2 helpers (Blackwell 2x FP32 path) -------------
// Each 64-bit register holds two independent fp32 lanes; fma.rn.f32x2 performs
// two IEEE fp32 fma.rn ops -> per-lane results bitwise-identical to scalar FFMA.
__device__ __forceinline__ void ffma2(unsigned long long &d,
                                      unsigned long long a, unsigned long long b) {
    asm("fma.rn.f32x2 %0, %1, %2, %0;" : "+l"(d) : "l"(a), "l"(b));
}
__device__ __forceinline__ unsigned long long pack2(float x) {
    unsigned long long r;
    asm("mov.b64 %0, {%1, %1};" : "=l"(r) : "r"(__float_as_uint(x)));
    return r;
}
__device__ __forceinline__ void unpack2(unsigned long long v, float &lo, float &hi) {
    asm("mov.b64 {%0, %1}, %2;" : "=f"(lo), "=f"(hi) : "l"(v));
}

// ---------------- fp32 GEMM body: C(MxN) = A(MxK) @ B(KxN) ----------------
// 128x128 tile, 256 threads, 8x8 micro; packed f32x2 accumulators paired along
// columns. Per-element accumulation stays kk-sequential -> bitwise-stable.
__device__ __forceinline__ void sgemm_body(
    const float* __restrict__ A, const float* __restrict__ Bm,
    float* __restrict__ C, int Ndim, int Kdim, int brow, int bcol)
{
    __shared__ float As[128*36];   // [m][k] pad 36 (16B-aligned kk groups)
    __shared__ float Bs[32*132];   // [k][n] pad 132 (528B rows, 16B-aligned)
    int tid  = threadIdx.x;
    int rowg = tid >> 4;             // 0..15
    int c0   = (tid & 15) * 4;       // 0..60
    unsigned long long acc2[8][4];   // [row][colpair]: (c,c+1) per reg
#pragma unroll
    for (int i = 0; i < 8; i++)
#pragma unroll
        for (int j = 0; j < 4; j++) acc2[i][j] = 0ull;

    for (int kt = 0; kt < Kdim; kt += 32) {
#pragma unroll
        for (int i = 0; i < 4; i++) {
            int f4 = tid + i*256;
            int r = f4 >> 3, c4 = f4 & 7;
            float4 v = *(const float4*)(A + (size_t)(brow + r)*Kdim + kt + c4*4);
            *(float4*)&As[r*36 + c4*4] = v;
        }
#pragma unroll
        for (int i = 0; i < 4; i++) {
            int f4 = tid + i*256;
            int r = f4 >> 5, c4 = f4 & 31;
            *(float4*)&Bs[r*132 + c4*4] =
                *(const float4*)(Bm + (size_t)(kt + r)*Ndim + bcol + c4*4);
        }
        __syncthreads();
#pragma unroll
        for (int k4 = 0; k4 < 8; k4++) {
            float4 a4[8];
#pragma unroll
            for (int i = 0; i < 8; i++)
                a4[i] = *(float4*)&As[(rowg + 16*i)*36 + k4*4];
#pragma unroll
            for (int j = 0; j < 4; j++) {
                int kk = k4*4 + j;
                ulonglong2 b0 = *(const ulonglong2*)&Bs[kk*132 + c0];
                ulonglong2 b1 = *(const ulonglong2*)&Bs[kk*132 + 64 + c0];
#pragma unroll
                for (int i = 0; i < 8; i++) {
                    float av = (j == 0) ? a4[i].x : (j == 1) ? a4[i].y
                             : (j == 2) ? a4[i].z : a4[i].w;
                    unsigned long long ap = pack2(av);
                    ffma2(acc2[i][0], ap, b0.x);
                    ffma2(acc2[i][1], ap, b0.y);
                    ffma2(acc2[i][2], ap, b1.x);
                    ffma2(acc2[i][3], ap, b1.y);
                }
            }
        }
        __syncthreads();
    }
#pragma unroll
    for (int i = 0; i < 8; i++) {
        size_t r = (size_t)(brow + rowg + 16*i)*Ndim + bcol;
        *(ulonglong2*)(C + r + c0)      = make_ulonglong2(acc2[i][0], acc2[i][1]);
        *(ulonglong2*)(C + r + 64 + c0) = make_ulonglong2(acc2[i][2], acc2[i][3]);
    }
}

// z=0: A0@B0 -> C0 (N0 cols). z=1: A1@B1 -> C1 (128 cols, blockIdx.x==0 only).
__global__ __launch_bounds__(256) void sgemm2_kernel(
    const float* __restrict__ A0, const float* __restrict__ B0, float* __restrict__ C0,
    const float* __restrict__ A1, const float* __restrict__ B1, float* __restrict__ C1,
    int N0, int Kdim)
{
    if (blockIdx.z == 0) {
        sgemm_body(A0, B0, C0, N0, Kdim, blockIdx.y*128, blockIdx.x*128);
    } else {
        if (blockIdx.x != 0) return;
        sgemm_body(A1, B1, C1, 128, Kdim, blockIdx.y*128, 0);
    }
}

// ---------------- sequence-axis L2 norm of k,v columns ----------------
__global__ void colsq_kernel() {
    int b = blockIdx.x >> 4, chunk = blockIdx.x & 15;
    int j = threadIdx.x & 127, p = threadIdx.x >> 7;
    const float* base = g_kv + ((size_t)b*LL + chunk*128)*128;
    float ss = 0.f;
    for (int ll = p; ll < 128; ll += 2) {
        float v = base[ll*128 + j];
        ss += v*v;
    }
    __shared__ float sh[256];
    sh[threadIdx.x] = ss;
    __syncthreads();
    if (p == 0) g_part[(size_t)blockIdx.x*128 + j] = ss + sh[128 + j];
}

__global__ void normalize_kernel() {  // grid 2048, 256 thr
    int idx = blockIdx.x*256 + threadIdx.x;
    int j  = idx & 127;
    int bl = idx >> 7;
    int b  = bl >> 11;
    float s = 0.f;
#pragma unroll
    for (int c = 0; c < 16; c++) s += g_part[(b*16 + c)*128 + j];
    float n = sqrtf(s);
    n = fmaxf(n, 1e-12f);
    float v = g_kv[(size_t)idx] / n;
    if (j < 64) g_k[(size_t)bl*64 + j]        = v;
    else        g_v[(size_t)bl*64 + (j - 64)] = v;
}

// ---------------- sims = q @ k^T (packed f32x2) ----------------
// grid (mtile 16, ltile 16, z 32). 128x128 tile, K=64, 8x8 micro.
__global__ __launch_bounds__(256) void sims_kernel() {
    extern __shared__ float sm[];
    float* Qs = sm;              // [128][68]  (l-rows x k)
    float* Kt = sm + 128*68;     // [64][132]  (k x m-rows, transposed; 528B rows)
    int z = blockIdx.z, b = z >> 4, h = z & 15;
    int lbase = blockIdx.y * 128, mbase = blockIdx.x * 128;
    const float* Aq = g_q + (size_t)b*LL*DD + h*DH;
    const float* Bk = g_k + (size_t)b*LL*DH;
    float* Cs = g_sims + (size_t)z*LL*LL;
    int tid = threadIdx.x;
#pragma unroll
    for (int i = 0; i < 8; i++) {            // Q tile 128x64
        int f4 = tid + i*256;
        int r = f4 >> 4, c4 = f4 & 15;
        float4 v = *(const float4*)(Aq + (size_t)(lbase + r)*DD + c4*4);
        *(float4*)&Qs[r*68 + c4*4] = v;
    }
#pragma unroll
    for (int i = 0; i < 8; i++) {            // K tile 128x64 -> transposed
        int f4 = tid + i*256;
        int lo = f4 & 31, hi = f4 >> 5;
        int r  = (lo & 7) + 8*(hi & 15);     // 0..127
        int c4 = (lo >> 3) + 4*(hi >> 4);    // 0..15
        float4 v = *(const float4*)(Bk + (size_t)(mbase + r)*DH + c4*4);
        Kt[(c4*4+0)*132 + r] = v.x; Kt[(c4*4+1)*132 + r] = v.y;
        Kt[(c4*4+2)*132 + r] = v.z; Kt[(c4*4+3)*132 + r] = v.w;
    }
    __syncthreads();
    int rowg = tid >> 4, c0 = (tid & 15)*4;
    unsigned long long acc2[8][4];
#pragma unroll
    for (int i = 0; i < 8; i++)
#pragma unroll
        for (int j = 0; j < 4; j++) acc2[i][j] = 0ull;
#pragma unroll
    for (int k4 = 0; k4 < 16; k4++) {
        float4 a4[8];
#pragma unroll
        for (int i = 0; i < 8; i++)
            a4[i] = *(float4*)&Qs[(rowg + 16*i)*68 + k4*4];
#pragma unroll
        for (int j = 0; j < 4; j++) {
            int kk = k4*4 + j;
            ulonglong2 b0 = *(const ulonglong2*)&Kt[kk*132 + c0];
            ulonglong2 b1 = *(const ulonglong2*)&Kt[kk*132 + 64 + c0];
#pragma unroll
            for (int i = 0; i < 8; i++) {
                float av = (j == 0) ? a4[i].x : (j == 1) ? a4[i].y
                         : (j == 2) ? a4[i].z : a4[i].w;
                unsigned long long ap = pack2(av);
                ffma2(acc2[i][0], ap, b0.x);
                ffma2(acc2[i][1], ap, b0.y);
                ffma2(acc2[i][2], ap, b1.x);
                ffma2(acc2[i][3], ap, b1.y);
            }
        }
    }
#pragma unroll
    for (int i = 0; i < 8; i++) {
        size_t off = (size_t)(lbase + rowg + 16*i)*LL + mbase;
        *(ulonglong2*)(Cs + off + c0)      = make_ulonglong2(acc2[i][0], acc2[i][1]);
        *(ulonglong2*)(Cs + off + 64 + c0) = make_ulonglong2(acc2[i][2], acc2[i][3]);
    }
}

// ---------------- per-row: max + exact top-32 ----------------
__global__ __launch_bounds__(256) void stats_topk_kernel() {  // grid 65536
    __shared__ unsigned cand_key[256];
    __shared__ int      cand_idx[256];
    __shared__ unsigned redk[8];
    size_t row = blockIdx.x;
    const float* S = g_sims + row * LL;
    int tid = threadIdx.x, lane = tid & 31, wid = tid >> 5;

    float4 a = ((const float4*)S)[tid];
    float4 c = ((const float4*)S)[tid + 256];
    float v[8] = {a.x, a.y, a.z, a.w, c.x, c.y, c.z, c.w};
    unsigned key[8];
#pragma unroll
    for (int j = 0; j < 8; j++) key[j] = f2key(v[j]);

    unsigned km = key[0];
#pragma unroll
    for (int j = 1; j < 8; j++) km = max(km, key[j]);
    km = __reduce_max_sync(0xffffffffu, km);
    if (lane == 0) redk[wid] = km;
    __syncthreads();
    if (tid == 0) {
        unsigned m = redk[0];
        for (int w = 1; w < 8; w++) m = max(m, redk[w]);
        g_rowmax[row] = key2f(m);
    }

    unsigned lk = 0; int lj = 0;
#pragma unroll
    for (int j = 0; j < 8; j++) if (key[j] > lk) { lk = key[j]; lj = j; }
    for (int it = 0; it < TK; it++) {
        unsigned w = __reduce_max_sync(0xffffffffu, lk);
        unsigned ball = __ballot_sync(0xffffffffu, lk == w);
        int src = __ffs(ball) - 1;
        if (lane == src) {
            cand_key[wid*32 + it] = w;
            cand_idx[wid*32 + it] = (lj < 4) ? (4*tid + lj) : (1024 + 4*tid + lj - 4);
            key[lj] = 0u;
            lk = 0; lj = 0;
#pragma unroll
            for (int j = 0; j < 8; j++) if (key[j] > lk) { lk = key[j]; lj = j; }
        }
    }
    __syncthreads();

    if (wid == 0) {
        unsigned mkey[8]; int midx[8];
#pragma unroll
        for (int j = 0; j < 8; j++) {
            mkey[j] = cand_key[lane*8 + j];
            midx[j] = cand_idx[lane*8 + j];
        }
        unsigned mk = 0; int mj = 0;
#pragma unroll
        for (int j = 0; j < 8; j++) if (mkey[j] > mk) { mk = mkey[j]; mj = j; }
        for (int it = 0; it < TK; it++) {
            unsigned w = __reduce_max_sync(0xffffffffu, mk);
            unsigned ball = __ballot_sync(0xffffffffu, mk == w);
            int src = __ffs(ball) - 1;
            if (lane == src) {
                g_topv[row*TK + it] = key2f(w);
                g_topi[row*TK + it] = midx[mj];
                mkey[mj] = 0u;
                mk = 0; mj = 0;
#pragma unroll
                for (int j = 0; j < 8; j++) if (mkey[j] > mk) { mk = mkey[j]; mj = j; }
            }
        }
    }
}

// ---------------- local = (sum_m e_m v_m)/(sum_m e_m), packed f32x2 ---------
// Accumulator pairs along ROWS (Pt is row-contiguous); bv broadcast packed.
__global__ __launch_bounds__(256) void pv_kernel() {
    extern __shared__ float sm[];
    float* Pt   = sm;                 // [64][260] (1040B rows, 16B-aligned)
    float* Vs   = sm + 64*260;        // [64][68]
    float* smx  = Vs + 64*68;         // [256] rowmax
    float* part = smx + 256;          // [4][256] rowsum partials
    float* rsin = part + 1024;        // [256] 1/rowsum
    int z = blockIdx.y, b = z >> 4, h = z & 15;
    int lbase = blockIdx.x * 256;
    const float* S = g_sims + (size_t)z*LL*LL;
    int tid = threadIdx.x;
    smx[tid] = g_rowmax[(size_t)z*LL + lbase + tid];
    __syncthreads();
    int rowg4 = (tid >> 4)*4;
    int c0    = (tid & 15)*4;
    // acc2[q*2+p][c]: lanes = rows (q*64+rowg4+2p, +2p+1), column c0+c
    unsigned long long acc2[8][4];
#pragma unroll
    for (int i = 0; i < 8; i++)
#pragma unroll
        for (int j = 0; j < 4; j++) acc2[i][j] = 0ull;
    float psum[4] = {0.f, 0.f, 0.f, 0.f};

    for (int mt = 0; mt < LL; mt += 64) {
#pragma unroll
        for (int i = 0; i < 16; i++) {
            int f4 = tid + i*256;
            int r  = (f4 & 7) + 8*((f4 >> 5) & 31);
            int c4 = ((f4 >> 3) & 3) + 4*(f4 >> 10);
            float4 v = *(const float4*)(S + (size_t)(lbase + r)*LL + mt + c4*4);
            float m = smx[r];
            float e0 = __expf((v.x - m)*SCALE);
            float e1 = __expf((v.y - m)*SCALE);
            float e2 = __expf((v.z - m)*SCALE);
            float e3 = __expf((v.w - m)*SCALE);
            Pt[(c4*4+0)*260 + r] = e0;
            Pt[(c4*4+1)*260 + r] = e1;
            Pt[(c4*4+2)*260 + r] = e2;
            Pt[(c4*4+3)*260 + r] = e3;
            psum[i & 3] += (e0 + e1) + (e2 + e3);
        }
#pragma unroll
        for (int i = 0; i < 4; i++) {
            int f4 = tid + i*256;
            int r = f4 >> 4, c4 = f4 & 15;
            *(float4*)&Vs[r*68 + c4*4] =
                *(const float4*)(g_v + ((size_t)b*LL + mt + r)*DH + c4*4);
        }
        __syncthreads();
#pragma unroll 8
        for (int ml = 0; ml < 64; ml++) {
            ulonglong2 a0 = *(const ulonglong2*)&Pt[ml*260 + rowg4];
            ulonglong2 a1 = *(const ulonglong2*)&Pt[ml*260 + 64  + rowg4];
            ulonglong2 a2 = *(const ulonglong2*)&Pt[ml*260 + 128 + rowg4];
            ulonglong2 a3 = *(const ulonglong2*)&Pt[ml*260 + 192 + rowg4];
            float4 bv = *(float4*)&Vs[ml*68 + c0];
            unsigned long long bp0 = pack2(bv.x), bp1 = pack2(bv.y);
            unsigned long long bp2 = pack2(bv.z), bp3 = pack2(bv.w);
            unsigned long long ap[8] = {a0.x, a0.y, a1.x, a1.y,
                                        a2.x, a2.y, a3.x, a3.y};
#pragma unroll
            for (int i = 0; i < 8; i++) {
                ffma2(acc2[i][0], ap[i], bp0);
                ffma2(acc2[i][1], ap[i], bp1);
                ffma2(acc2[i][2], ap[i], bp2);
                ffma2(acc2[i][3], ap[i], bp3);
            }
        }
        __syncthreads();
    }

#pragma unroll
    for (int ii = 0; ii < 4; ii++) part[ii*256 + tid] = psum[ii];
    __syncthreads();
    {
        int rho = tid;
        int ii  = rho >> 6;
        float s = 0.f;
#pragma unroll
        for (int k = 0; k < 4; k++) {
            int t = (rho & 7) | (k << 3) | (((rho >> 3) & 7) << 5);
            s += part[ii*256 + t];
        }
        rsin[rho] = 1.0f / s;
    }
    __syncthreads();

#pragma unroll
    for (int q = 0; q < 4; q++)
#pragma unroll
        for (int p = 0; p < 2; p++) {
            float lo0, hi0, lo1, hi1, lo2, hi2, lo3, hi3;
            unpack2(acc2[q*2+p][0], lo0, hi0);
            unpack2(acc2[q*2+p][1], lo1, hi1);
            unpack2(acc2[q*2+p][2], lo2, hi2);
            unpack2(acc2[q*2+p][3], lo3, hi3);
            int rl0 = q*64 + rowg4 + 2*p;
            float iv0 = rsin[rl0], iv1 = rsin[rl0 + 1];
            *(float4*)(g_attn + ((size_t)b*LL + lbase + rl0)*DD + h*DH + c0) =
                make_float4(lo0*iv0, lo1*iv0, lo2*iv0, lo3*iv0);
            *(float4*)(g_attn + ((size_t)b*LL + lbase + rl0 + 1)*DD + h*DH + c0) =
                make_float4(hi0*iv1, hi1*iv1, hi2*iv1, hi3*iv1);
        }
}

// ---------------- retrieved = softmax(topv*scale) @ k[topi] ----------------
__global__ __launch_bounds__(256) void retrieved_kernel() {
    __shared__ float ps[8][32];
    __shared__ int   tis[8][32];
    int wid = threadIdx.x >> 5, lane = threadIdx.x & 31;
    size_t row = (size_t)blockIdx.x*8 + wid;
    int z = (int)(row >> 11), l = (int)(row & 2047);
    int b = z >> 4, h = z & 15;
    float tv = g_topv[row*TK + lane];
    int   ti = g_topi[row*TK + lane];
    float mx = __shfl_sync(0xffffffffu, tv, 0);
    float p = __expf((tv - mx)*SCALE);
    float psum = p;
#pragma unroll
    for (int o = 16; o; o >>= 1) psum += __shfl_xor_sync(0xffffffffu, psum, o);
    ps[wid][lane] = p / psum;
    tis[wid][lane] = ti;
    __syncwarp();
    const float* kb = g_k + (size_t)b*LL*DH;
    float a0 = 0.f, a1 = 0.f;
#pragma unroll 8
    for (int t = 0; t < TK; t++) {
        float w = ps[wid][t];
        const float* kr = kb + (size_t)tis[wid][t]*DH;
        a0 += w * kr[lane];
        a1 += w * kr[lane + 32];
    }
    size_t off = ((size_t)b*LL + l)*DD + h*DH;
    g_attn[off + lane]      += a0;
    g_attn[off + lane + 32] += a1;
}

// ---------------- launch ----------------
extern "C" void kernel_launch(void* const* d_in, const int* in_sizes, int n_in,
                              void* d_out, int out_size)
{
    const float* q_in     = (const float*)d_in[0];
    const float* kv_in    = (const float*)d_in[1];
    const float* w_q      = (const float*)d_in[2];
    const float* w_kv     = (const float*)d_in[3];
    const float* w_concat = (const float*)d_in[4];
    float* out = (float*)d_out;

    float *p_q, *p_kv, *p_attn;
    cudaGetSymbolAddress((void**)&p_q,    g_q);
    cudaGetSymbolAddress((void**)&p_kv,   g_kv);
    cudaGetSymbolAddress((void**)&p_attn, g_attn);

    static const int SIMS_SMEM = (128*68 + 64*132)*4;                     // 68608
    static const int PV_SMEM   = (64*260 + 64*68 + 256 + 1024 + 256)*4;   // 90112
    cudaFuncSetAttribute(sims_kernel, cudaFuncAttributeMaxDynamicSharedMemorySize, SIMS_SMEM);
    cudaFuncSetAttribute(pv_kernel,   cudaFuncAttributeMaxDynamicSharedMemorySize, PV_SMEM);

    // 1. q = q_in @ w_q (z=0) and kv = kv_in @ w_kv (z=1), one launch
    sgemm2_kernel<<<dim3(8, 32, 2), 256>>>(q_in, w_q, p_q, kv_in, w_kv, p_kv, DD, DD);
    // 2-3. l2 norm over sequence axis
    colsq_kernel<<<32, 256>>>();
    normalize_kernel<<<2048, 256>>>();
    // 4. sims (f32x2) — ncu capture slot
    sims_kernel<<<dim3(16, 16, 32), 256, SIMS_SMEM>>>();
    // 5. row max + exact top-32
    stats_topk_kernel<<<BB*HH*LL, 256>>>();
    // 6. local attention (flash-normalized P@V, f32x2) -> g_attn
    pv_kernel<<<dim3(8, 32), 256, PV_SMEM>>>();
    // 7. retrieved (+= into g_attn)
    retrieved_kernel<<<BB*HH*LL/8, 256>>>();
    // 8. out = attn @ w_concat
    sgemm2_kernel<<<dim3(8, 32, 1), 256>>>(p_attn, w_concat, out, p_attn, w_concat, out, DD, DD);
}

// round 16
// speedup vs baseline: 1.9823x; 1.0319x over previous
#include <cuda_runtime.h>
#include <math.h>
#include <stdint.h>

#define BB 2
#define LL 2048
#define DD 1024
#define HH 16
#define DH 64
#define TK 32
#define SCALE 0.125f   // 1/sqrt(64)

// ---------------- scratch (device globals; no allocs allowed) ----------------
__device__ float g_q   [(size_t)BB*LL*DD];
__device__ float g_kv  [(size_t)BB*LL*2*DH];
__device__ float g_k   [(size_t)BB*LL*DH];
__device__ float g_v   [(size_t)BB*LL*DH];
__device__ float g_part[BB*16*128];
__device__ float g_sims[(size_t)BB*HH*LL*LL];       // 512 MB
__device__ float g_rowmax[BB*HH*LL];
__device__ float g_topv[(size_t)BB*HH*LL*TK];
__device__ int   g_topi[(size_t)BB*HH*LL*TK];
__device__ float g_attn[(size_t)BB*LL*DD];

// ordered-uint key helpers (monotone float <-> uint map)
__device__ __forceinline__ unsigned f2key(float x) {
    unsigned u = __float_as_uint(x);
    return u ^ ((unsigned)((int)u >> 31) | 0x80000000u);
}
__device__ __forceinline__ float key2f(unsigned k) {
    unsigned u = (k & 0x80000000u) ? (k ^ 0x80000000u) : ~k;
    return __uint_as_float(u);
}

// ---------------- packed f32x2 helpers (Blackwell 2x FP32 path) -------------
__device__ __forceinline__ void ffma2(unsigned long long &d,
                                      unsigned long long a, unsigned long long b) {
    asm("fma.rn.f32x2 %0, %1, %2, %0;" : "+l"(d) : "l"(a), "l"(b));
}
__device__ __forceinline__ unsigned long long pack2(float x) {
    unsigned long long r;
    asm("mov.b64 %0, {%1, %1};" : "=l"(r) : "r"(__float_as_uint(x)));
    return r;
}
__device__ __forceinline__ void unpack2(unsigned long long v, float &lo, float &hi) {
    asm("mov.b64 {%0, %1}, %2;" : "=f"(lo), "=f"(hi) : "l"(v));
}

// ---------------- fp32 GEMM body: C(MxN) = A(MxK) @ B(KxN) ----------------
// 128x128 tile, 256 threads, 8x8 micro; f32x2 accumulators paired along cols.
// i-loop split in halves (a4[4] live at a time) to stay under 128 regs.
// Per-element accumulation stays kk-sequential ascending -> bitwise-stable.
__device__ __forceinline__ void sgemm_body(
    const float* __restrict__ A, const float* __restrict__ Bm,
    float* __restrict__ C, int Ndim, int Kdim, int brow, int bcol)
{
    __shared__ float As[128*36];   // [m][k] pad 36
    __shared__ float Bs[32*132];   // [k][n] pad 132
    int tid  = threadIdx.x;
    int rowg = tid >> 4;             // 0..15
    int c0   = (tid & 15) * 4;       // 0..60
    unsigned long long acc2[8][4];   // [row][colpair]
#pragma unroll
    for (int i = 0; i < 8; i++)
#pragma unroll
        for (int j = 0; j < 4; j++) acc2[i][j] = 0ull;

    for (int kt = 0; kt < Kdim; kt += 32) {
#pragma unroll
        for (int i = 0; i < 4; i++) {
            int f4 = tid + i*256;
            int r = f4 >> 3, c4 = f4 & 7;
            float4 v = *(const float4*)(A + (size_t)(brow + r)*Kdim + kt + c4*4);
            *(float4*)&As[r*36 + c4*4] = v;
        }
#pragma unroll
        for (int i = 0; i < 4; i++) {
            int f4 = tid + i*256;
            int r = f4 >> 5, c4 = f4 & 31;
            *(float4*)&Bs[r*132 + c4*4] =
                *(const float4*)(Bm + (size_t)(kt + r)*Ndim + bcol + c4*4);
        }
        __syncthreads();
#pragma unroll
        for (int k4 = 0; k4 < 8; k4++) {
#pragma unroll
            for (int half = 0; half < 2; half++) {
                float4 a4[4];
#pragma unroll
                for (int i = 0; i < 4; i++)
                    a4[i] = *(float4*)&As[(rowg + 16*(half*4 + i))*36 + k4*4];
#pragma unroll
                for (int j = 0; j < 4; j++) {
                    int kk = k4*4 + j;
                    ulonglong2 b0 = *(const ulonglong2*)&Bs[kk*132 + c0];
                    ulonglong2 b1 = *(const ulonglong2*)&Bs[kk*132 + 64 + c0];
#pragma unroll
                    for (int i = 0; i < 4; i++) {
                        float av = (j == 0) ? a4[i].x : (j == 1) ? a4[i].y
                                 : (j == 2) ? a4[i].z : a4[i].w;
                        unsigned long long ap = pack2(av);
                        ffma2(acc2[half*4 + i][0], ap, b0.x);
                        ffma2(acc2[half*4 + i][1], ap, b0.y);
                        ffma2(acc2[half*4 + i][2], ap, b1.x);
                        ffma2(acc2[half*4 + i][3], ap, b1.y);
                    }
                }
            }
        }
        __syncthreads();
    }
#pragma unroll
    for (int i = 0; i < 8; i++) {
        size_t r = (size_t)(brow + rowg + 16*i)*Ndim + bcol;
        *(ulonglong2*)(C + r + c0)      = make_ulonglong2(acc2[i][0], acc2[i][1]);
        *(ulonglong2*)(C + r + 64 + c0) = make_ulonglong2(acc2[i][2], acc2[i][3]);
    }
}

// z=0: A0@B0 -> C0 (N0 cols). z=1: A1@B1 -> C1 (128 cols, blockIdx.x==0 only).
__global__ __launch_bounds__(256, 2) void sgemm2_kernel(
    const float* __restrict__ A0, const float* __restrict__ B0, float* __restrict__ C0,
    const float* __restrict__ A1, const float* __restrict__ B1, float* __restrict__ C1,
    int N0, int Kdim)
{
    if (blockIdx.z == 0) {
        sgemm_body(A0, B0, C0, N0, Kdim, blockIdx.y*128, blockIdx.x*128);
    } else {
        if (blockIdx.x != 0) return;
        sgemm_body(A1, B1, C1, 128, Kdim, blockIdx.y*128, 0);
    }
}

// ---------------- sequence-axis L2 norm of k,v columns ----------------
__global__ void colsq_kernel() {
    int b = blockIdx.x >> 4, chunk = blockIdx.x & 15;
    int j = threadIdx.x & 127, p = threadIdx.x >> 7;
    const float* base = g_kv + ((size_t)b*LL + chunk*128)*128;
    float ss = 0.f;
    for (int ll = p; ll < 128; ll += 2) {
        float v = base[ll*128 + j];
        ss += v*v;
    }
    __shared__ float sh[256];
    sh[threadIdx.x] = ss;
    __syncthreads();
    if (p == 0) g_part[(size_t)blockIdx.x*128 + j] = ss + sh[128 + j];
}

__global__ void normalize_kernel() {  // grid 2048, 256 thr
    int idx = blockIdx.x*256 + threadIdx.x;
    int j  = idx & 127;
    int bl = idx >> 7;
    int b  = bl >> 11;
    float s = 0.f;
#pragma unroll
    for (int c = 0; c < 16; c++) s += g_part[(b*16 + c)*128 + j];
    float n = sqrtf(s);
    n = fmaxf(n, 1e-12f);
    float v = g_kv[(size_t)idx] / n;
    if (j < 64) g_k[(size_t)bl*64 + j]        = v;
    else        g_v[(size_t)bl*64 + (j - 64)] = v;
}

// ---------------- sims = q @ k^T (packed f32x2, 2 CTAs/SM) ----------------
// grid (mtile 16, ltile 16, z 32). 128x128 tile, K=64, 8x8 micro.
__global__ __launch_bounds__(256, 2) void sims_kernel() {
    extern __shared__ float sm[];
    float* Qs = sm;              // [128][68]
    float* Kt = sm + 128*68;     // [64][132]
    int z = blockIdx.z, b = z >> 4, h = z & 15;
    int lbase = blockIdx.y * 128, mbase = blockIdx.x * 128;
    const float* Aq = g_q + (size_t)b*LL*DD + h*DH;
    const float* Bk = g_k + (size_t)b*LL*DH;
    float* Cs = g_sims + (size_t)z*LL*LL;
    int tid = threadIdx.x;
#pragma unroll
    for (int i = 0; i < 8; i++) {            // Q tile 128x64
        int f4 = tid + i*256;
        int r = f4 >> 4, c4 = f4 & 15;
        float4 v = *(const float4*)(Aq + (size_t)(lbase + r)*DD + c4*4);
        *(float4*)&Qs[r*68 + c4*4] = v;
    }
#pragma unroll
    for (int i = 0; i < 8; i++) {            // K tile 128x64 -> transposed
        int f4 = tid + i*256;
        int lo = f4 & 31, hi = f4 >> 5;
        int r  = (lo & 7) + 8*(hi & 15);
        int c4 = (lo >> 3) + 4*(hi >> 4);
        float4 v = *(const float4*)(Bk + (size_t)(mbase + r)*DH + c4*4);
        Kt[(c4*4+0)*132 + r] = v.x; Kt[(c4*4+1)*132 + r] = v.y;
        Kt[(c4*4+2)*132 + r] = v.z; Kt[(c4*4+3)*132 + r] = v.w;
    }
    __syncthreads();
    int rowg = tid >> 4, c0 = (tid & 15)*4;
    unsigned long long acc2[8][4];
#pragma unroll
    for (int i = 0; i < 8; i++)
#pragma unroll
        for (int j = 0; j < 4; j++) acc2[i][j] = 0ull;
#pragma unroll
    for (int k4 = 0; k4 < 16; k4++) {
#pragma unroll
        for (int half = 0; half < 2; half++) {
            float4 a4[4];
#pragma unroll
            for (int i = 0; i < 4; i++)
                a4[i] = *(float4*)&Qs[(rowg + 16*(half*4 + i))*68 + k4*4];
#pragma unroll
            for (int j = 0; j < 4; j++) {
                int kk = k4*4 + j;
                ulonglong2 b0 = *(const ulonglong2*)&Kt[kk*132 + c0];
                ulonglong2 b1 = *(const ulonglong2*)&Kt[kk*132 + 64 + c0];
#pragma unroll
                for (int i = 0; i < 4; i++) {
                    float av = (j == 0) ? a4[i].x : (j == 1) ? a4[i].y
                             : (j == 2) ? a4[i].z : a4[i].w;
                    unsigned long long ap = pack2(av);
                    ffma2(acc2[half*4 + i][0], ap, b0.x);
                    ffma2(acc2[half*4 + i][1], ap, b0.y);
                    ffma2(acc2[half*4 + i][2], ap, b1.x);
                    ffma2(acc2[half*4 + i][3], ap, b1.y);
                }
            }
        }
    }
#pragma unroll
    for (int i = 0; i < 8; i++) {
        size_t off = (size_t)(lbase + rowg + 16*i)*LL + mbase;
        *(ulonglong2*)(Cs + off + c0)      = make_ulonglong2(acc2[i][0], acc2[i][1]);
        *(ulonglong2*)(Cs + off + 64 + c0) = make_ulonglong2(acc2[i][2], acc2[i][3]);
    }
}

// ---------------- per-row: max + exact top-32 ----------------
__global__ __launch_bounds__(256) void stats_topk_kernel() {  // grid 65536
    __shared__ unsigned cand_key[256];
    __shared__ int      cand_idx[256];
    __shared__ unsigned redk[8];
    size_t row = blockIdx.x;
    const float* S = g_sims + row * LL;
    int tid = threadIdx.x, lane = tid & 31, wid = tid >> 5;

    float4 a = ((const float4*)S)[tid];
    float4 c = ((const float4*)S)[tid + 256];
    float v[8] = {a.x, a.y, a.z, a.w, c.x, c.y, c.z, c.w};
    unsigned key[8];
#pragma unroll
    for (int j = 0; j < 8; j++) key[j] = f2key(v[j]);

    unsigned km = key[0];
#pragma unroll
    for (int j = 1; j < 8; j++) km = max(km, key[j]);
    km = __reduce_max_sync(0xffffffffu, km);
    if (lane == 0) redk[wid] = km;
    __syncthreads();
    if (tid == 0) {
        unsigned m = redk[0];
        for (int w = 1; w < 8; w++) m = max(m, redk[w]);
        g_rowmax[row] = key2f(m);
    }

    unsigned lk = 0; int lj = 0;
#pragma unroll
    for (int j = 0; j < 8; j++) if (key[j] > lk) { lk = key[j]; lj = j; }
    for (int it = 0; it < TK; it++) {
        unsigned w = __reduce_max_sync(0xffffffffu, lk);
        unsigned ball = __ballot_sync(0xffffffffu, lk == w);
        int src = __ffs(ball) - 1;
        if (lane == src) {
            cand_key[wid*32 + it] = w;
            cand_idx[wid*32 + it] = (lj < 4) ? (4*tid + lj) : (1024 + 4*tid + lj - 4);
            key[lj] = 0u;
            lk = 0; lj = 0;
#pragma unroll
            for (int j = 0; j < 8; j++) if (key[j] > lk) { lk = key[j]; lj = j; }
        }
    }
    __syncthreads();

    if (wid == 0) {
        unsigned mkey[8]; int midx[8];
#pragma unroll
        for (int j = 0; j < 8; j++) {
            mkey[j] = cand_key[lane*8 + j];
            midx[j] = cand_idx[lane*8 + j];
        }
        unsigned mk = 0; int mj = 0;
#pragma unroll
        for (int j = 0; j < 8; j++) if (mkey[j] > mk) { mk = mkey[j]; mj = j; }
        for (int it = 0; it < TK; it++) {
            unsigned w = __reduce_max_sync(0xffffffffu, mk);
            unsigned ball = __ballot_sync(0xffffffffu, mk == w);
            int src = __ffs(ball) - 1;
            if (lane == src) {
                g_topv[row*TK + it] = key2f(w);
                g_topi[row*TK + it] = midx[mj];
                mkey[mj] = 0u;
                mk = 0; mj = 0;
#pragma unroll
                for (int j = 0; j < 8; j++) if (mkey[j] > mk) { mk = mkey[j]; mj = j; }
            }
        }
    }
}

// ---------------- local = (sum_m e_m v_m)/(sum_m e_m), packed f32x2 ---------
__global__ __launch_bounds__(256, 2) void pv_kernel() {
    extern __shared__ float sm[];
    float* Pt   = sm;                 // [64][260]
    float* Vs   = sm + 64*260;        // [64][68]
    float* smx  = Vs + 64*68;         // [256]
    float* part = smx + 256;          // [4][256]
    float* rsin = part + 1024;        // [256]
    int z = blockIdx.y, b = z >> 4, h = z & 15;
    int lbase = blockIdx.x * 256;
    const float* S = g_sims + (size_t)z*LL*LL;
    int tid = threadIdx.x;
    smx[tid] = g_rowmax[(size_t)z*LL + lbase + tid];
    __syncthreads();
    int rowg4 = (tid >> 4)*4;
    int c0    = (tid & 15)*4;
    unsigned long long acc2[8][4];
#pragma unroll
    for (int i = 0; i < 8; i++)
#pragma unroll
        for (int j = 0; j < 4; j++) acc2[i][j] = 0ull;
    float psum[4] = {0.f, 0.f, 0.f, 0.f};

    for (int mt = 0; mt < LL; mt += 64) {
#pragma unroll
        for (int i = 0; i < 16; i++) {
            int f4 = tid + i*256;
            int r  = (f4 & 7) + 8*((f4 >> 5) & 31);
            int c4 = ((f4 >> 3) & 3) + 4*(f4 >> 10);
            float4 v = *(const float4*)(S + (size_t)(lbase + r)*LL + mt + c4*4);
            float m = smx[r];
            float e0 = __expf((v.x - m)*SCALE);
            float e1 = __expf((v.y - m)*SCALE);
            float e2 = __expf((v.z - m)*SCALE);
            float e3 = __expf((v.w - m)*SCALE);
            Pt[(c4*4+0)*260 + r] = e0;
            Pt[(c4*4+1)*260 + r] = e1;
            Pt[(c4*4+2)*260 + r] = e2;
            Pt[(c4*4+3)*260 + r] = e3;
            psum[i & 3] += (e0 + e1) + (e2 + e3);
        }
#pragma unroll
        for (int i = 0; i < 4; i++) {
            int f4 = tid + i*256;
            int r = f4 >> 4, c4 = f4 & 15;
            *(float4*)&Vs[r*68 + c4*4] =
                *(const float4*)(g_v + ((size_t)b*LL + mt + r)*DH + c4*4);
        }
        __syncthreads();
#pragma unroll 8
        for (int ml = 0; ml < 64; ml++) {
            ulonglong2 a0 = *(const ulonglong2*)&Pt[ml*260 + rowg4];
            ulonglong2 a1 = *(const ulonglong2*)&Pt[ml*260 + 64  + rowg4];
            ulonglong2 a2 = *(const ulonglong2*)&Pt[ml*260 + 128 + rowg4];
            ulonglong2 a3 = *(const ulonglong2*)&Pt[ml*260 + 192 + rowg4];
            float4 bv = *(float4*)&Vs[ml*68 + c0];
            unsigned long long bp0 = pack2(bv.x), bp1 = pack2(bv.y);
            unsigned long long bp2 = pack2(bv.z), bp3 = pack2(bv.w);
            unsigned long long ap[8] = {a0.x, a0.y, a1.x, a1.y,
                                        a2.x, a2.y, a3.x, a3.y};
#pragma unroll
            for (int i = 0; i < 8; i++) {
                ffma2(acc2[i][0], ap[i], bp0);
                ffma2(acc2[i][1], ap[i], bp1);
                ffma2(acc2[i][2], ap[i], bp2);
                ffma2(acc2[i][3], ap[i], bp3);
            }
        }
        __syncthreads();
    }

#pragma unroll
    for (int ii = 0; ii < 4; ii++) part[ii*256 + tid] = psum[ii];
    __syncthreads();
    {
        int rho = tid;
        int ii  = rho >> 6;
        float s = 0.f;
#pragma unroll
        for (int k = 0; k < 4; k++) {
            int t = (rho & 7) | (k << 3) | (((rho >> 3) & 7) << 5);
            s += part[ii*256 + t];
        }
        rsin[rho] = 1.0f / s;
    }
    __syncthreads();

#pragma unroll
    for (int q = 0; q < 4; q++)
#pragma unroll
        for (int p = 0; p < 2; p++) {
            float lo0, hi0, lo1, hi1, lo2, hi2, lo3, hi3;
            unpack2(acc2[q*2+p][0], lo0, hi0);
            unpack2(acc2[q*2+p][1], lo1, hi1);
            unpack2(acc2[q*2+p][2], lo2, hi2);
            unpack2(acc2[q*2+p][3], lo3, hi3);
            int rl0 = q*64 + rowg4 + 2*p;
            float iv0 = rsin[rl0], iv1 = rsin[rl0 + 1];
            *(float4*)(g_attn + ((size_t)b*LL + lbase + rl0)*DD + h*DH + c0) =
                make_float4(lo0*iv0, lo1*iv0, lo2*iv0, lo3*iv0);
            *(float4*)(g_attn + ((size_t)b*LL + lbase + rl0 + 1)*DD + h*DH + c0) =
                make_float4(hi0*iv1, hi1*iv1, hi2*iv1, hi3*iv1);
        }
}

// ---------------- retrieved = softmax(topv*scale) @ k[topi] ----------------
__global__ __launch_bounds__(256) void retrieved_kernel() {
    __shared__ float ps[8][32];
    __shared__ int   tis[8][32];
    int wid = threadIdx.x >> 5, lane = threadIdx.x & 31;
    size_t row = (size_t)blockIdx.x*8 + wid;
    int z = (int)(row >> 11), l = (int)(row & 2047);
    int b = z >> 4, h = z & 15;
    float tv = g_topv[row*TK + lane];
    int   ti = g_topi[row*TK + lane];
    float mx = __shfl_sync(0xffffffffu, tv, 0);
    float p = __expf((tv - mx)*SCALE);
    float psum = p;
#pragma unroll
    for (int o = 16; o; o >>= 1) psum += __shfl_xor_sync(0xffffffffu, psum, o);
    ps[wid][lane] = p / psum;
    tis[wid][lane] = ti;
    __syncwarp();
    const float* kb = g_k + (size_t)b*LL*DH;
    float a0 = 0.f, a1 = 0.f;
#pragma unroll 8
    for (int t = 0; t < TK; t++) {
        float w = ps[wid][t];
        const float* kr = kb + (size_t)tis[wid][t]*DH;
        a0 += w * kr[lane];
        a1 += w * kr[lane + 32];
    }
    size_t off = ((size_t)b*LL + l)*DD + h*DH;
    g_attn[off + lane]      += a0;
    g_attn[off + lane + 32] += a1;
}

// ---------------- launch ----------------
extern "C" void kernel_launch(void* const* d_in, const int* in_sizes, int n_in,
                              void* d_out, int out_size)
{
    const float* q_in     = (const float*)d_in[0];
    const float* kv_in    = (const float*)d_in[1];
    const float* w_q      = (const float*)d_in[2];
    const float* w_kv     = (const float*)d_in[3];
    const float* w_concat = (const float*)d_in[4];
    float* out = (float*)d_out;

    float *p_q, *p_kv, *p_attn;
    cudaGetSymbolAddress((void**)&p_q,    g_q);
    cudaGetSymbolAddress((void**)&p_kv,   g_kv);
    cudaGetSymbolAddress((void**)&p_attn, g_attn);

    static const int SIMS_SMEM = (128*68 + 64*132)*4;                     // 68608
    static const int PV_SMEM   = (64*260 + 64*68 + 256 + 1024 + 256)*4;   // 90112
    cudaFuncSetAttribute(sims_kernel, cudaFuncAttributeMaxDynamicSharedMemorySize, SIMS_SMEM);
    cudaFuncSetAttribute(pv_kernel,   cudaFuncAttributeMaxDynamicSharedMemorySize, PV_SMEM);

    // 1. q = q_in @ w_q (z=0) and kv = kv_in @ w_kv (z=1), one launch
    sgemm2_kernel<<<dim3(8, 32, 2), 256>>>(q_in, w_q, p_q, kv_in, w_kv, p_kv, DD, DD);
    // 2-3. l2 norm over sequence axis
    colsq_kernel<<<32, 256>>>();
    normalize_kernel<<<2048, 256>>>();
    // 4. sims (f32x2, 2 CTAs/SM) — ncu capture slot
    sims_kernel<<<dim3(16, 16, 32), 256, SIMS_SMEM>>>();
    // 5. row max + exact top-32
    stats_topk_kernel<<<BB*HH*LL, 256>>>();
    // 6. local attention (flash-normalized P@V, f32x2) -> g_attn
    pv_kernel<<<dim3(8, 32), 256, PV_SMEM>>>();
    // 7. retrieved (+= into g_attn)
    retrieved_kernel<<<BB*HH*LL/8, 256>>>();
    // 8. out = attn @ w_concat
    sgemm2_kernel<<<dim3(8, 32, 1), 256>>>(p_attn, w_concat, out, p_attn, w_concat, out, DD, DD);
}